// round 1
// baseline (speedup 1.0000x reference)
#include <cuda_runtime.h>
#include <math.h>

#define NN 50000
#define NE 625000
#define NGR 64
#define HC 128
#define FC 128
#define NGAUSS 50
#define NLAY 6
#define TILE_E 128
#define TILE_N 64

// ---------------- scratch (device globals; no allocation allowed) ----------
__device__ float g_demb[(long)NE * NGAUSS];   // [E, 50] gaussian embedding
__device__ float g_C[NE];                     // cosine cutoff
__device__ float g_v[NN * HC];                // node features
__device__ float g_x[NN * HC];                // v @ lin_W[l]
__device__ float g_agg[NN * HC];              // scatter-add target
__device__ float g_tmp[NN * HC];              // ssp(agg @ vW1 + b1)

__device__ __forceinline__ float ssp_f(float x) {
    // softplus(x) - log(2), numerically stable
    return fmaxf(x, 0.0f) + log1pf(expf(-fabsf(x))) - 0.69314718055994531f;
}

// ---------------- init: v = emb_table[z] -----------------------------------
__global__ void init_v_kernel(const int* __restrict__ z, const float* __restrict__ emb) {
    int idx = blockIdx.x * blockDim.x + threadIdx.x;
    if (idx < NN * HC) {
        int n = idx >> 7;
        int h = idx & 127;
        g_v[idx] = emb[z[n] * HC + h];
    }
}

// ---------------- per-edge precompute: dist, C, dist_emb --------------------
__global__ void edge_pre_kernel(const float* __restrict__ pos, const int* __restrict__ eidx) {
    int e = blockIdx.x * blockDim.x + threadIdx.x;
    if (e >= NE) return;
    int r = eidx[e];         // row = j (source)
    int c = eidx[NE + e];    // col = i (target)
    float dx = pos[3 * r + 0] - pos[3 * c + 0];
    float dy = pos[3 * r + 1] - pos[3 * c + 1];
    float dz = pos[3 * r + 2] - pos[3 * c + 2];
    float dist = sqrtf(dx * dx + dy * dy + dz * dz);
    g_C[e] = 0.5f * (cosf(dist * 0.31415926535897931f) + 1.0f);   // PI/CUTOFF
    const float delta = 10.0f / 49.0f;
    const float coeff = -0.5f / (delta * delta);
    long base = (long)e * NGAUSS;
    #pragma unroll
    for (int g = 0; g < NGAUSS; g++) {
        float d = dist - (float)g * delta;
        g_demb[base + g] = expf(coeff * d * d);
    }
}

__global__ void zero_agg_kernel() {
    for (int i = blockIdx.x * blockDim.x + threadIdx.x; i < NN * HC; i += gridDim.x * blockDim.x)
        g_agg[i] = 0.0f;
}

__global__ void zero_out_kernel(float* __restrict__ out) {
    int i = threadIdx.x;
    if (i < NGR) out[i] = 0.0f;
}

// ---------------- fused edge kernel per layer -------------------------------
// W = (ssp(demb @ W1 + b1) @ W2 + b2) * C ; e = x[row]*W ; atomicAdd agg[col]
// Persistent blocks: weights loaded into smem once, loop over edge tiles.
__global__ void __launch_bounds__(512, 1)
edge_layer_kernel(const float* __restrict__ W1, const float* __restrict__ b1,
                  const float* __restrict__ W2, const float* __restrict__ b2,
                  const int* __restrict__ eidx)
{
    extern __shared__ float s[];
    float* sW1 = s;                              // 50*128   = 6400
    float* sW2 = sW1 + NGAUSS * FC;              // 128*128  = 16384
    float* sD  = sW2 + FC * FC;                  // 128*51   = 6528 (pad 51)
    float* sT  = sD + TILE_E * 51;               // 128*129  = 16512 (pad 129)

    int tid = threadIdx.x;
    for (int i = tid; i < NGAUSS * FC; i += 512) sW1[i] = W1[i];
    for (int i = tid; i < FC * FC; i += 512)     sW2[i] = W2[i];

    int fg = tid & 15;           // filter group -> 8 cols
    int eg = tid >> 4;           // edge group   -> 4 edges
    int c0 = fg * 8;
    int er = eg * 4;

    float bb1[8], bb2[8];
    #pragma unroll
    for (int j = 0; j < 8; j++) { bb1[j] = b1[c0 + j]; bb2[j] = b2[c0 + j]; }

    int ntiles = (NE + TILE_E - 1) / TILE_E;
    for (int t = blockIdx.x; t < ntiles; t += gridDim.x) {
        int e0 = t * TILE_E;
        __syncthreads();   // prev iter done reading sD/sT
        for (int i = tid; i < TILE_E * NGAUSS; i += 512) {
            int r = i / NGAUSS, c = i - r * NGAUSS;
            int e = e0 + r;
            sD[r * 51 + c] = (e < NE) ? g_demb[(long)e * NGAUSS + c] : 0.0f;
        }
        __syncthreads();

        // GEMM1: t = demb @ W1  (K = 50)
        float a[4][8];
        #pragma unroll
        for (int i = 0; i < 4; i++)
            #pragma unroll
            for (int j = 0; j < 8; j++) a[i][j] = 0.0f;

        #pragma unroll 10
        for (int k = 0; k < NGAUSS; k++) {
            float4 wa = *(const float4*)(sW1 + k * FC + c0);
            float4 wb = *(const float4*)(sW1 + k * FC + c0 + 4);
            float d0 = sD[(er + 0) * 51 + k];
            float d1 = sD[(er + 1) * 51 + k];
            float d2 = sD[(er + 2) * 51 + k];
            float d3 = sD[(er + 3) * 51 + k];
            a[0][0] += d0 * wa.x; a[0][1] += d0 * wa.y; a[0][2] += d0 * wa.z; a[0][3] += d0 * wa.w;
            a[0][4] += d0 * wb.x; a[0][5] += d0 * wb.y; a[0][6] += d0 * wb.z; a[0][7] += d0 * wb.w;
            a[1][0] += d1 * wa.x; a[1][1] += d1 * wa.y; a[1][2] += d1 * wa.z; a[1][3] += d1 * wa.w;
            a[1][4] += d1 * wb.x; a[1][5] += d1 * wb.y; a[1][6] += d1 * wb.z; a[1][7] += d1 * wb.w;
            a[2][0] += d2 * wa.x; a[2][1] += d2 * wa.y; a[2][2] += d2 * wa.z; a[2][3] += d2 * wa.w;
            a[2][4] += d2 * wb.x; a[2][5] += d2 * wb.y; a[2][6] += d2 * wb.z; a[2][7] += d2 * wb.w;
            a[3][0] += d3 * wa.x; a[3][1] += d3 * wa.y; a[3][2] += d3 * wa.z; a[3][3] += d3 * wa.w;
            a[3][4] += d3 * wb.x; a[3][5] += d3 * wb.y; a[3][6] += d3 * wb.z; a[3][7] += d3 * wb.w;
        }
        // bias + ssp -> sT
        #pragma unroll
        for (int i = 0; i < 4; i++)
            #pragma unroll
            for (int j = 0; j < 8; j++)
                sT[(er + i) * 129 + c0 + j] = ssp_f(a[i][j] + bb1[j]);
        __syncthreads();

        // GEMM2: W = sT @ W2  (K = 128)
        float a2[4][8];
        #pragma unroll
        for (int i = 0; i < 4; i++)
            #pragma unroll
            for (int j = 0; j < 8; j++) a2[i][j] = 0.0f;

        #pragma unroll 8
        for (int k = 0; k < FC; k++) {
            float4 wa = *(const float4*)(sW2 + k * FC + c0);
            float4 wb = *(const float4*)(sW2 + k * FC + c0 + 4);
            float t0 = sT[(er + 0) * 129 + k];
            float t1 = sT[(er + 1) * 129 + k];
            float t2 = sT[(er + 2) * 129 + k];
            float t3 = sT[(er + 3) * 129 + k];
            a2[0][0] += t0 * wa.x; a2[0][1] += t0 * wa.y; a2[0][2] += t0 * wa.z; a2[0][3] += t0 * wa.w;
            a2[0][4] += t0 * wb.x; a2[0][5] += t0 * wb.y; a2[0][6] += t0 * wb.z; a2[0][7] += t0 * wb.w;
            a2[1][0] += t1 * wa.x; a2[1][1] += t1 * wa.y; a2[1][2] += t1 * wa.z; a2[1][3] += t1 * wa.w;
            a2[1][4] += t1 * wb.x; a2[1][5] += t1 * wb.y; a2[1][6] += t1 * wb.z; a2[1][7] += t1 * wb.w;
            a2[2][0] += t2 * wa.x; a2[2][1] += t2 * wa.y; a2[2][2] += t2 * wa.z; a2[2][3] += t2 * wa.w;
            a2[2][4] += t2 * wb.x; a2[2][5] += t2 * wb.y; a2[2][6] += t2 * wb.z; a2[2][7] += t2 * wb.w;
            a2[3][0] += t3 * wa.x; a2[3][1] += t3 * wa.y; a2[3][2] += t3 * wa.z; a2[3][3] += t3 * wa.w;
            a2[3][4] += t3 * wb.x; a2[3][5] += t3 * wb.y; a2[3][6] += t3 * wb.z; a2[3][7] += t3 * wb.w;
        }

        // epilogue: *C, gather x[row], scatter-add agg[col]
        #pragma unroll
        for (int i = 0; i < 4; i++) {
            int e = e0 + er + i;
            if (e >= NE) continue;
            float ce = g_C[e];
            int rj = eidx[e];
            int ci = eidx[NE + e];
            const float* xr = g_x + (long)rj * HC + c0;
            float4 xa = *(const float4*)(xr);
            float4 xb = *(const float4*)(xr + 4);
            float xv[8] = {xa.x, xa.y, xa.z, xa.w, xb.x, xb.y, xb.z, xb.w};
            float* ap = g_agg + (long)ci * HC + c0;
            #pragma unroll
            for (int j = 0; j < 8; j++) {
                float w = (a2[i][j] + bb2[j]) * ce;
                atomicAdd(ap + j, w * xv[j]);
            }
        }
    }
}

// ---------------- node GEMM: Y = f(X @ W [+ b] [+ res]) ---------------------
// mode 0: g_x   = g_v   @ W                (no bias/act)
// mode 1: g_tmp = ssp(g_agg @ W + b)
// mode 2: g_v   = g_v + g_tmp @ W + b
__global__ void __launch_bounds__(256, 2)
node_gemm_kernel(const float* __restrict__ W, const float* __restrict__ bias, int mode)
{
    extern __shared__ float s[];
    float* sW = s;                 // 128*128 = 16384
    float* sX = s + FC * FC;       // 64*129

    const float* X = (mode == 0) ? g_v : (mode == 1) ? g_agg : g_tmp;
    float*       Y = (mode == 0) ? g_x : (mode == 1) ? g_tmp : g_v;

    int tid = threadIdx.x;
    int n0 = blockIdx.x * TILE_N;
    for (int i = tid; i < HC * FC; i += 256) sW[i] = W[i];
    for (int i = tid; i < TILE_N * HC; i += 256) {
        int r = i >> 7, c = i & 127;
        int n = n0 + r;
        sX[r * 129 + c] = (n < NN) ? X[(long)n * HC + c] : 0.0f;
    }
    __syncthreads();

    int fg = tid & 15, eg = tid >> 4;
    int c0 = fg * 8, nr = eg * 4;

    float a[4][8];
    #pragma unroll
    for (int i = 0; i < 4; i++)
        #pragma unroll
        for (int j = 0; j < 8; j++) a[i][j] = 0.0f;

    #pragma unroll 8
    for (int k = 0; k < HC; k++) {
        float4 wa = *(const float4*)(sW + k * FC + c0);
        float4 wb = *(const float4*)(sW + k * FC + c0 + 4);
        float x0 = sX[(nr + 0) * 129 + k];
        float x1 = sX[(nr + 1) * 129 + k];
        float x2 = sX[(nr + 2) * 129 + k];
        float x3 = sX[(nr + 3) * 129 + k];
        a[0][0] += x0 * wa.x; a[0][1] += x0 * wa.y; a[0][2] += x0 * wa.z; a[0][3] += x0 * wa.w;
        a[0][4] += x0 * wb.x; a[0][5] += x0 * wb.y; a[0][6] += x0 * wb.z; a[0][7] += x0 * wb.w;
        a[1][0] += x1 * wa.x; a[1][1] += x1 * wa.y; a[1][2] += x1 * wa.z; a[1][3] += x1 * wa.w;
        a[1][4] += x1 * wb.x; a[1][5] += x1 * wb.y; a[1][6] += x1 * wb.z; a[1][7] += x1 * wb.w;
        a[2][0] += x2 * wa.x; a[2][1] += x2 * wa.y; a[2][2] += x2 * wa.z; a[2][3] += x2 * wa.w;
        a[2][4] += x2 * wb.x; a[2][5] += x2 * wb.y; a[2][6] += x2 * wb.z; a[2][7] += x2 * wb.w;
        a[3][0] += x3 * wa.x; a[3][1] += x3 * wa.y; a[3][2] += x3 * wa.z; a[3][3] += x3 * wa.w;
        a[3][4] += x3 * wb.x; a[3][5] += x3 * wb.y; a[3][6] += x3 * wb.z; a[3][7] += x3 * wb.w;
    }

    #pragma unroll
    for (int i = 0; i < 4; i++) {
        int n = n0 + nr + i;
        if (n >= NN) continue;
        float* yp = Y + (long)n * HC + c0;
        if (mode == 0) {
            float4 o0 = make_float4(a[i][0], a[i][1], a[i][2], a[i][3]);
            float4 o1 = make_float4(a[i][4], a[i][5], a[i][6], a[i][7]);
            *(float4*)(yp) = o0;
            *(float4*)(yp + 4) = o1;
        } else if (mode == 1) {
            #pragma unroll
            for (int j = 0; j < 8; j++)
                yp[j] = ssp_f(a[i][j] + bias[c0 + j]);
        } else {
            #pragma unroll
            for (int j = 0; j < 8; j++)
                yp[j] = yp[j] + a[i][j] + bias[c0 + j];
        }
    }
}

// ---------------- readout: h = ssp(v@uW1+b1)@uW2+b2 ; segment_sum by batch --
__global__ void readout_kernel(const int* __restrict__ batch,
                               const float* __restrict__ uW1, const float* __restrict__ ub1,
                               const float* __restrict__ uW2, const float* __restrict__ ub2,
                               float* __restrict__ out)
{
    __shared__ float sv[8][HC];
    int tid = threadIdx.x;
    int w = tid >> 5, l = tid & 31;
    int n0 = blockIdx.x * 8;
    for (int i = tid; i < 8 * HC; i += 256) {
        int r = i >> 7;
        int n = n0 + r;
        sv[r][i & 127] = (n < NN) ? g_v[(long)n * HC + (i & 127)] : 0.0f;
    }
    __syncthreads();
    int n = n0 + w;
    if (n >= NN) return;
    float a0 = 0.0f, a1 = 0.0f;
    #pragma unroll 8
    for (int h = 0; h < HC; h++) {
        float vv = sv[w][h];
        a0 += vv * uW1[h * 64 + l];
        a1 += vv * uW1[h * 64 + l + 32];
    }
    float h0 = ssp_f(a0 + ub1[l]);
    float h1 = ssp_f(a1 + ub1[l + 32]);
    float p = h0 * uW2[l] + h1 * uW2[l + 32];
    #pragma unroll
    for (int o = 16; o; o >>= 1) p += __shfl_down_sync(0xffffffffu, p, o);
    if (l == 0) atomicAdd(&out[batch[n]], p + ub2[0]);
}

// ---------------- launch ----------------------------------------------------
extern "C" void kernel_launch(void* const* d_in, const int* in_sizes, int n_in,
                              void* d_out, int out_size)
{
    const int*   z     = (const int*)d_in[0];
    const float* pos   = (const float*)d_in[1];
    const int*   batch = (const int*)d_in[2];
    const int*   eidx  = (const int*)d_in[3];
    const float* emb   = (const float*)d_in[4];
    const float* lin_W = (const float*)d_in[5];
    const float* mW1   = (const float*)d_in[6];
    const float* mb1   = (const float*)d_in[7];
    const float* mW2   = (const float*)d_in[8];
    const float* mb2   = (const float*)d_in[9];
    const float* vW1   = (const float*)d_in[10];
    const float* vb1   = (const float*)d_in[11];
    const float* vW2   = (const float*)d_in[12];
    const float* vb2   = (const float*)d_in[13];
    const float* uW1   = (const float*)d_in[14];
    const float* ub1   = (const float*)d_in[15];
    const float* uW2   = (const float*)d_in[16];
    const float* ub2   = (const float*)d_in[17];
    float* out = (float*)d_out;

    const int EDGE_SMEM = (NGAUSS * FC + FC * FC + TILE_E * 51 + TILE_E * 129) * (int)sizeof(float);
    const int NODE_SMEM = (FC * FC + TILE_N * 129) * (int)sizeof(float);
    cudaFuncSetAttribute(edge_layer_kernel, cudaFuncAttributeMaxDynamicSharedMemorySize, EDGE_SMEM);
    cudaFuncSetAttribute(node_gemm_kernel, cudaFuncAttributeMaxDynamicSharedMemorySize, NODE_SMEM);

    init_v_kernel<<<(NN * HC + 255) / 256, 256>>>(z, emb);
    edge_pre_kernel<<<(NE + 255) / 256, 256>>>(pos, eidx);

    const int NODE_GRID = (NN + TILE_N - 1) / TILE_N;   // 782
    for (int l = 0; l < NLAY; l++) {
        node_gemm_kernel<<<NODE_GRID, 256, NODE_SMEM>>>(lin_W + (long)l * HC * FC, nullptr, 0);
        zero_agg_kernel<<<1024, 256>>>();
        edge_layer_kernel<<<148, 512, EDGE_SMEM>>>(mW1 + (long)l * NGAUSS * FC,
                                                   mb1 + (long)l * FC,
                                                   mW2 + (long)l * FC * FC,
                                                   mb2 + (long)l * FC,
                                                   eidx);
        node_gemm_kernel<<<NODE_GRID, 256, NODE_SMEM>>>(vW1 + (long)l * FC * HC, vb1 + (long)l * HC, 1);
        node_gemm_kernel<<<NODE_GRID, 256, NODE_SMEM>>>(vW2 + (long)l * HC * HC, vb2 + (long)l * HC, 2);
    }

    zero_out_kernel<<<1, 64>>>(out);
    readout_kernel<<<(NN + 7) / 8, 256>>>(batch, uW1, ub1, uW2, ub2, out);
    (void)in_sizes; (void)n_in; (void)out_size;
}

// round 3
// speedup vs baseline: 1.8078x; 1.8078x over previous
#include <cuda_runtime.h>
#include <math.h>
#include <stdint.h>

#define NN 50000
#define NE 625000
#define NE_TILES 4883                 // ceil(NE/128)
#define NE_PAD (NE_TILES * 128)
#define NGR 64
#define HC 128
#define FC 128
#define NGAUSS 50
#define KG 56                         // gaussian K padded to 56 (mult of 8)
#define NLAY 6
#define TILE_N 64

// smem strides (floats) — chosen for conflict-free fragment loads
#define SA 60     // sD stride   (bank = 28g+r : all distinct)
#define SB 132    // weight strides (bank = 4r+g : all distinct)
#define ST 132    // sT stride

// ---------------- scratch (device globals; no allocation allowed) ----------
__device__ float g_demb[(size_t)NE_PAD * KG];   // tf32-rounded gaussian emb [E][56]
__device__ float g_C[NE];
__device__ float g_v[NN * HC];
__device__ float g_x[NN * HC];
__device__ float g_agg[NN * HC];
__device__ float g_tmp[NN * HC];
__device__ float g_W1t[NLAY * KG * FC];   // [l][k][n] tf32-rounded, zero-padded
__device__ float g_W2t[NLAY * FC * FC];   // [l][k][n] tf32-rounded

// ---------------- helpers ---------------------------------------------------
__device__ __forceinline__ uint32_t f2tf32(float x) {
    uint32_t r;
    asm("cvt.rna.tf32.f32 %0, %1;" : "=r"(r) : "f"(x));
    return r;
}
__device__ __forceinline__ void mma8(float* c, const uint32_t* a, uint32_t b0, uint32_t b1) {
    asm volatile("mma.sync.aligned.m16n8k8.row.col.f32.tf32.tf32.f32 "
                 "{%0,%1,%2,%3},{%4,%5,%6,%7},{%8,%9},{%0,%1,%2,%3};"
                 : "+f"(c[0]), "+f"(c[1]), "+f"(c[2]), "+f"(c[3])
                 : "r"(a[0]), "r"(a[1]), "r"(a[2]), "r"(a[3]), "r"(b0), "r"(b1));
}
__device__ __forceinline__ void red2(float* p, float a, float b) {
    asm volatile("red.global.add.v2.f32 [%0], {%1,%2};" :: "l"(p), "f"(a), "f"(b) : "memory");
}
__device__ __forceinline__ float ssp_f(float x) {
    return fmaxf(x, 0.0f) + log1pf(expf(-fabsf(x))) - 0.69314718055994531f;
}
__device__ __forceinline__ float ssp_fast(float x) {
    return fmaxf(x, 0.0f) + __logf(1.0f + __expf(-fabsf(x))) - 0.69314718055994531f;
}

// ---------------- init: v = emb_table[z] -----------------------------------
__global__ void init_v_kernel(const int* __restrict__ z, const float* __restrict__ emb) {
    int idx = blockIdx.x * blockDim.x + threadIdx.x;
    if (idx < NN * HC) g_v[idx] = emb[z[idx >> 7] * HC + (idx & 127)];
}

// ---------------- per-edge precompute: C + tf32 gaussian rows ---------------
__global__ void edge_pre_kernel(const float* __restrict__ pos, const int* __restrict__ eidx) {
    int e = blockIdx.x * blockDim.x + threadIdx.x;
    if (e >= NE_PAD) return;
    bool valid = e < NE;
    float dist = 0.0f;
    if (valid) {
        int r = eidx[e], c = eidx[NE + e];
        float dx = pos[3 * r] - pos[3 * c];
        float dy = pos[3 * r + 1] - pos[3 * c + 1];
        float dz = pos[3 * r + 2] - pos[3 * c + 2];
        dist = sqrtf(dx * dx + dy * dy + dz * dz);
        g_C[e] = 0.5f * (cosf(dist * 0.31415926535897931f) + 1.0f);
    }
    const float delta = 10.0f / 49.0f;
    const float coeff = -0.5f / (delta * delta);
    float* row = g_demb + (size_t)e * KG;
    #pragma unroll
    for (int k = 0; k < KG; k++) {
        float d = dist - (float)k * delta;
        float v = (valid && k < NGAUSS) ? __expf(coeff * d * d) : 0.0f;
        row[k] = __uint_as_float(f2tf32(v));
    }
}

// ---------------- prep: tf32-round weights into padded [k][n] layout --------
__global__ void prep_w_kernel(const float* __restrict__ mW1, const float* __restrict__ mW2) {
    int idx = blockIdx.x * blockDim.x + threadIdx.x;
    if (idx < NLAY * KG * FC) {
        int l = idx / (KG * FC), rem = idx % (KG * FC);
        int k = rem / FC, n = rem % FC;
        float v = (k < NGAUSS) ? mW1[(l * NGAUSS + k) * FC + n] : 0.0f;
        g_W1t[idx] = __uint_as_float(f2tf32(v));
    }
    if (idx < NLAY * FC * FC) {
        g_W2t[idx] = __uint_as_float(f2tf32(mW2[idx]));
    }
}

__global__ void zero_agg_kernel() {
    for (int i = blockIdx.x * blockDim.x + threadIdx.x; i < NN * HC; i += gridDim.x * blockDim.x)
        g_agg[i] = 0.0f;
}
__global__ void zero_out_kernel(float* __restrict__ out) {
    if (threadIdx.x < NGR) out[threadIdx.x] = 0.0f;
}

// ---------------- fused edge kernel (mma.sync tf32) -------------------------
// smem float offsets
#define OFF_SW1 0
#define OFF_SW2 (OFF_SW1 + KG * SB)         // 7392
#define OFF_SD  (OFF_SW2 + FC * SB)         // 24288
#define OFF_STT (OFF_SD + 128 * SA)         // 31968
#define OFF_SB1 (OFF_STT + 128 * ST)        // 48864
#define OFF_SB2 (OFF_SB1 + FC)
#define EDGE_SMEM_F (OFF_SB2 + FC)          // 49120 floats = 196480 B

__global__ void __launch_bounds__(256, 1)
edge_layer_wmma(const float* __restrict__ b1, const float* __restrict__ b2,
                const int* __restrict__ eidx, int l)
{
    extern __shared__ float s[];
    float* sW1 = s + OFF_SW1;
    float* sW2 = s + OFF_SW2;
    float* sD  = s + OFF_SD;
    float* sT  = s + OFF_STT;
    float* sB1 = s + OFF_SB1;
    float* sB2 = s + OFF_SB2;

    int tid = threadIdx.x;
    int wid = tid >> 5, lane = tid & 31;
    int g = lane >> 2, r = lane & 3;
    int wm = wid & 3, wn = wid >> 2;     // warp tile: rows wm*32..+31, cols wn*64..+63

    // stage weights (pad stride SB) + biases
    {
        const float* w1 = g_W1t + (size_t)l * KG * FC;
        const float* w2 = g_W2t + (size_t)l * FC * FC;
        for (int i = tid; i < KG * FC; i += 256) sW1[(i >> 7) * SB + (i & 127)] = w1[i];
        for (int i = tid; i < FC * FC; i += 256) sW2[(i >> 7) * SB + (i & 127)] = w2[i];
        for (int i = tid; i < FC; i += 256) { sB1[i] = b1[i]; sB2[i] = b2[i]; }
    }
    __syncthreads();

    for (int t = blockIdx.x; t < NE_TILES; t += gridDim.x) {
        __syncthreads();   // prev-iter sT reads done before restage (sD) / rewrite (sT)
        // stage sD [128][56] -> stride SA
        {
            const float* src = g_demb + (size_t)t * 128 * KG;
            #pragma unroll 7
            for (int i = tid; i < 128 * KG; i += 256) {
                int row = i / KG, k = i - row * KG;
                sD[row * SA + k] = src[i];
            }
        }
        __syncthreads();

        // ---------------- GEMM1: [128,56] @ [56,128] -------------------------
        float c1[2][8][4];
        #pragma unroll
        for (int im = 0; im < 2; im++)
            #pragma unroll
            for (int jn = 0; jn < 8; jn++)
                #pragma unroll
                for (int q = 0; q < 4; q++) c1[im][jn][q] = 0.0f;

        #pragma unroll
        for (int kk = 0; kk < KG / 8; kk++) {
            uint32_t a[2][4];
            #pragma unroll
            for (int im = 0; im < 2; im++) {
                int rb = wm * 32 + im * 16 + g;
                int kb = kk * 8 + r;
                a[im][0] = __float_as_uint(sD[rb * SA + kb]);
                a[im][1] = __float_as_uint(sD[(rb + 8) * SA + kb]);
                a[im][2] = __float_as_uint(sD[rb * SA + kb + 4]);
                a[im][3] = __float_as_uint(sD[(rb + 8) * SA + kb + 4]);
            }
            #pragma unroll
            for (int jn = 0; jn < 8; jn++) {
                int nb = wn * 64 + jn * 8 + g;
                uint32_t b0 = __float_as_uint(sW1[(kk * 8 + r) * SB + nb]);
                uint32_t bv = __float_as_uint(sW1[(kk * 8 + 4 + r) * SB + nb]);
                mma8(c1[0][jn], a[0], b0, bv);
                mma8(c1[1][jn], a[1], b0, bv);
            }
        }

        // bias + ssp -> sT (tf32-rounded)
        #pragma unroll
        for (int im = 0; im < 2; im++) {
            int rb = wm * 32 + im * 16 + g;
            #pragma unroll
            for (int jn = 0; jn < 8; jn++) {
                int col = wn * 64 + jn * 8 + 2 * r;
                float bb0 = sB1[col], bb1 = sB1[col + 1];
                float2 lo, hi;
                lo.x = __uint_as_float(f2tf32(ssp_fast(c1[im][jn][0] + bb0)));
                lo.y = __uint_as_float(f2tf32(ssp_fast(c1[im][jn][1] + bb1)));
                hi.x = __uint_as_float(f2tf32(ssp_fast(c1[im][jn][2] + bb0)));
                hi.y = __uint_as_float(f2tf32(ssp_fast(c1[im][jn][3] + bb1)));
                *(float2*)(sT + rb * ST + col) = lo;
                *(float2*)(sT + (rb + 8) * ST + col) = hi;
            }
        }
        __syncthreads();

        // ---------------- GEMM2: [128,128] @ [128,128] -----------------------
        float c2[2][8][4];
        #pragma unroll
        for (int im = 0; im < 2; im++)
            #pragma unroll
            for (int jn = 0; jn < 8; jn++)
                #pragma unroll
                for (int q = 0; q < 4; q++) c2[im][jn][q] = 0.0f;

        #pragma unroll 4
        for (int kk = 0; kk < FC / 8; kk++) {
            uint32_t a[2][4];
            #pragma unroll
            for (int im = 0; im < 2; im++) {
                int rb = wm * 32 + im * 16 + g;
                int kb = kk * 8 + r;
                a[im][0] = __float_as_uint(sT[rb * ST + kb]);
                a[im][1] = __float_as_uint(sT[(rb + 8) * ST + kb]);
                a[im][2] = __float_as_uint(sT[rb * ST + kb + 4]);
                a[im][3] = __float_as_uint(sT[(rb + 8) * ST + kb + 4]);
            }
            #pragma unroll
            for (int jn = 0; jn < 8; jn++) {
                int nb = wn * 64 + jn * 8 + g;
                uint32_t b0 = __float_as_uint(sW2[(kk * 8 + r) * SB + nb]);
                uint32_t bv = __float_as_uint(sW2[(kk * 8 + 4 + r) * SB + nb]);
                mma8(c2[0][jn], a[0], b0, bv);
                mma8(c2[1][jn], a[1], b0, bv);
            }
        }

        // ---------------- epilogue: *C, gather x[row], red into agg[col] -----
        #pragma unroll
        for (int q = 0; q < 4; q++) {
            int im = q >> 1, hi = q & 1;
            int row = wm * 32 + im * 16 + hi * 8 + g;
            int e = t * 128 + row;
            if (e >= NE) continue;
            float Ce = g_C[e];
            int rj = eidx[e];
            int ci = eidx[NE + e];
            const float* xr = g_x + (size_t)rj * HC;
            float* ap = g_agg + (size_t)ci * HC;
            #pragma unroll
            for (int jn = 0; jn < 8; jn++) {
                int col = wn * 64 + jn * 8 + 2 * r;
                float w0 = (c2[im][jn][hi * 2 + 0] + sB2[col]) * Ce;
                float w1 = (c2[im][jn][hi * 2 + 1] + sB2[col + 1]) * Ce;
                float2 xv = *(const float2*)(xr + col);
                red2(ap + col, w0 * xv.x, w1 * xv.y);
            }
        }
    }
}

// ---------------- node GEMM (fp32 FFMA, proven in R1) -----------------------
__global__ void __launch_bounds__(256, 2)
node_gemm_kernel(const float* __restrict__ W, const float* __restrict__ bias, int mode)
{
    extern __shared__ float s[];
    float* sW = s;
    float* sX = s + FC * FC;

    const float* X = (mode == 0) ? g_v : (mode == 1) ? g_agg : g_tmp;
    float*       Y = (mode == 0) ? g_x : (mode == 1) ? g_tmp : g_v;

    int tid = threadIdx.x;
    int n0 = blockIdx.x * TILE_N;
    for (int i = tid; i < HC * FC; i += 256) sW[i] = W[i];
    for (int i = tid; i < TILE_N * HC; i += 256) {
        int rr = i >> 7, c = i & 127;
        int n = n0 + rr;
        sX[rr * 129 + c] = (n < NN) ? X[(size_t)n * HC + c] : 0.0f;
    }
    __syncthreads();

    int fg = tid & 15, eg = tid >> 4;
    int c0 = fg * 8, nr = eg * 4;

    float a[4][8];
    #pragma unroll
    for (int i = 0; i < 4; i++)
        #pragma unroll
        for (int j = 0; j < 8; j++) a[i][j] = 0.0f;

    #pragma unroll 8
    for (int k = 0; k < HC; k++) {
        float4 wa = *(const float4*)(sW + k * FC + c0);
        float4 wb = *(const float4*)(sW + k * FC + c0 + 4);
        float x0 = sX[(nr + 0) * 129 + k];
        float x1 = sX[(nr + 1) * 129 + k];
        float x2 = sX[(nr + 2) * 129 + k];
        float x3 = sX[(nr + 3) * 129 + k];
        a[0][0] += x0 * wa.x; a[0][1] += x0 * wa.y; a[0][2] += x0 * wa.z; a[0][3] += x0 * wa.w;
        a[0][4] += x0 * wb.x; a[0][5] += x0 * wb.y; a[0][6] += x0 * wb.z; a[0][7] += x0 * wb.w;
        a[1][0] += x1 * wa.x; a[1][1] += x1 * wa.y; a[1][2] += x1 * wa.z; a[1][3] += x1 * wa.w;
        a[1][4] += x1 * wb.x; a[1][5] += x1 * wb.y; a[1][6] += x1 * wb.z; a[1][7] += x1 * wb.w;
        a[2][0] += x2 * wa.x; a[2][1] += x2 * wa.y; a[2][2] += x2 * wa.z; a[2][3] += x2 * wa.w;
        a[2][4] += x2 * wb.x; a[2][5] += x2 * wb.y; a[2][6] += x2 * wb.z; a[2][7] += x2 * wb.w;
        a[3][0] += x3 * wa.x; a[3][1] += x3 * wa.y; a[3][2] += x3 * wa.z; a[3][3] += x3 * wa.w;
        a[3][4] += x3 * wb.x; a[3][5] += x3 * wb.y; a[3][6] += x3 * wb.z; a[3][7] += x3 * wb.w;
    }

    #pragma unroll
    for (int i = 0; i < 4; i++) {
        int n = n0 + nr + i;
        if (n >= NN) continue;
        float* yp = Y + (size_t)n * HC + c0;
        if (mode == 0) {
            *(float4*)(yp) = make_float4(a[i][0], a[i][1], a[i][2], a[i][3]);
            *(float4*)(yp + 4) = make_float4(a[i][4], a[i][5], a[i][6], a[i][7]);
        } else if (mode == 1) {
            #pragma unroll
            for (int j = 0; j < 8; j++) yp[j] = ssp_f(a[i][j] + bias[c0 + j]);
        } else {
            #pragma unroll
            for (int j = 0; j < 8; j++) yp[j] = yp[j] + a[i][j] + bias[c0 + j];
        }
    }
}

// ---------------- readout ---------------------------------------------------
__global__ void readout_kernel(const int* __restrict__ batch,
                               const float* __restrict__ uW1, const float* __restrict__ ub1,
                               const float* __restrict__ uW2, const float* __restrict__ ub2,
                               float* __restrict__ out)
{
    __shared__ float sv[8][HC];
    int tid = threadIdx.x;
    int w = tid >> 5, l = tid & 31;
    int n0 = blockIdx.x * 8;
    for (int i = tid; i < 8 * HC; i += 256) {
        int n = n0 + (i >> 7);
        sv[i >> 7][i & 127] = (n < NN) ? g_v[(size_t)n * HC + (i & 127)] : 0.0f;
    }
    __syncthreads();
    int n = n0 + w;
    if (n >= NN) return;
    float a0 = 0.0f, a1 = 0.0f;
    #pragma unroll 8
    for (int h = 0; h < HC; h++) {
        float vv = sv[w][h];
        a0 += vv * uW1[h * 64 + l];
        a1 += vv * uW1[h * 64 + l + 32];
    }
    float h0 = ssp_f(a0 + ub1[l]);
    float h1 = ssp_f(a1 + ub1[l + 32]);
    float p = h0 * uW2[l] + h1 * uW2[l + 32];
    #pragma unroll
    for (int o = 16; o; o >>= 1) p += __shfl_down_sync(0xffffffffu, p, o);
    if (l == 0) atomicAdd(&out[batch[n]], p + ub2[0]);
}

// ---------------- launch ----------------------------------------------------
extern "C" void kernel_launch(void* const* d_in, const int* in_sizes, int n_in,
                              void* d_out, int out_size)
{
    const int*   z     = (const int*)d_in[0];
    const float* pos   = (const float*)d_in[1];
    const int*   batch = (const int*)d_in[2];
    const int*   eidx  = (const int*)d_in[3];
    const float* emb   = (const float*)d_in[4];
    const float* lin_W = (const float*)d_in[5];
    const float* mW1   = (const float*)d_in[6];
    const float* mb1   = (const float*)d_in[7];
    const float* mW2   = (const float*)d_in[8];
    const float* mb2   = (const float*)d_in[9];
    const float* vW1   = (const float*)d_in[10];
    const float* vb1   = (const float*)d_in[11];
    const float* vW2   = (const float*)d_in[12];
    const float* vb2   = (const float*)d_in[13];
    const float* uW1   = (const float*)d_in[14];
    const float* ub1   = (const float*)d_in[15];
    const float* uW2   = (const float*)d_in[16];
    const float* ub2   = (const float*)d_in[17];
    float* out = (float*)d_out;

    const int EDGE_SMEM = EDGE_SMEM_F * (int)sizeof(float);
    const int NODE_SMEM = (FC * FC + TILE_N * 129) * (int)sizeof(float);
    cudaFuncSetAttribute(edge_layer_wmma, cudaFuncAttributeMaxDynamicSharedMemorySize, EDGE_SMEM);
    cudaFuncSetAttribute(node_gemm_kernel, cudaFuncAttributeMaxDynamicSharedMemorySize, NODE_SMEM);

    init_v_kernel<<<(NN * HC + 255) / 256, 256>>>(z, emb);
    edge_pre_kernel<<<(NE_PAD + 255) / 256, 256>>>(pos, eidx);
    prep_w_kernel<<<(NLAY * FC * FC + 255) / 256, 256>>>(mW1, mW2);

    const int NODE_GRID = (NN + TILE_N - 1) / TILE_N;
    for (int l = 0; l < NLAY; l++) {
        node_gemm_kernel<<<NODE_GRID, 256, NODE_SMEM>>>(lin_W + (size_t)l * HC * FC, nullptr, 0);
        zero_agg_kernel<<<1024, 256>>>();
        edge_layer_wmma<<<148, 256, EDGE_SMEM>>>(mb1 + (size_t)l * FC, mb2 + (size_t)l * FC, eidx, l);
        node_gemm_kernel<<<NODE_GRID, 256, NODE_SMEM>>>(vW1 + (size_t)l * FC * HC, vb1 + (size_t)l * HC, 1);
        node_gemm_kernel<<<NODE_GRID, 256, NODE_SMEM>>>(vW2 + (size_t)l * HC * HC, vb2 + (size_t)l * HC, 2);
    }

    zero_out_kernel<<<1, 64>>>(out);
    readout_kernel<<<(NN + 7) / 8, 256>>>(batch, uW1, ub1, uW2, ub2, out);
    (void)in_sizes; (void)n_in; (void)out_size;
}

// round 4
// speedup vs baseline: 2.0362x; 1.1263x over previous
#include <cuda_runtime.h>
#include <math.h>
#include <stdint.h>

#define NN 50000
#define NE 625000
#define NE_TILES 4883                 // ceil(NE/128)
#define NE_PAD (NE_TILES * 128)
#define NGR 64
#define HC 128
#define FC 128
#define NGAUSS 50
#define KG 56                         // gaussian K padded to 56 (mult of 8)
#define NLAY 6
#define NT 128                        // node tile rows

// smem strides (floats) — conflict-free fragment loads
#define SA 60     // sD stride
#define SB 132    // weight / activation stride
#define ST 132    // sT stride

// ---------------- scratch (device globals; no allocation allowed) ----------
__device__ float g_demb[(size_t)NE_PAD * KG];   // tf32-rounded gaussian emb [E][56]
__device__ float g_C[NE];
__device__ float g_v[NN * HC];
__device__ float g_x[NN * HC];
__device__ float g_agg[NN * HC];
__device__ float g_tmp[NN * HC];
__device__ float g_W1t[NLAY * KG * FC];   // [l][k][n] tf32-rounded, zero-padded
__device__ float g_W2t[NLAY * FC * FC];   // [l][k][n] tf32-rounded

// ---------------- helpers ---------------------------------------------------
__device__ __forceinline__ uint32_t f2tf32(float x) {
    uint32_t r;
    asm("cvt.rna.tf32.f32 %0, %1;" : "=r"(r) : "f"(x));
    return r;
}
__device__ __forceinline__ void mma8(float* c, const uint32_t* a, uint32_t b0, uint32_t b1) {
    asm volatile("mma.sync.aligned.m16n8k8.row.col.f32.tf32.tf32.f32 "
                 "{%0,%1,%2,%3},{%4,%5,%6,%7},{%8,%9},{%0,%1,%2,%3};"
                 : "+f"(c[0]), "+f"(c[1]), "+f"(c[2]), "+f"(c[3])
                 : "r"(a[0]), "r"(a[1]), "r"(a[2]), "r"(a[3]), "r"(b0), "r"(b1));
}
__device__ __forceinline__ void red2(float* p, float a, float b) {
    asm volatile("red.global.add.v2.f32 [%0], {%1,%2};" :: "l"(p), "f"(a), "f"(b) : "memory");
}
__device__ __forceinline__ float ssp_f(float x) {
    return fmaxf(x, 0.0f) + log1pf(expf(-fabsf(x))) - 0.69314718055994531f;
}
__device__ __forceinline__ float ssp_fast(float x) {
    return fmaxf(x, 0.0f) + __logf(1.0f + __expf(-fabsf(x))) - 0.69314718055994531f;
}

// ---------------- init: v = emb_table[z] -----------------------------------
__global__ void init_v_kernel(const int* __restrict__ z, const float* __restrict__ emb) {
    int idx = blockIdx.x * blockDim.x + threadIdx.x;
    if (idx < NN * HC) g_v[idx] = emb[z[idx >> 7] * HC + (idx & 127)];
}

// ---------------- per-edge precompute: C + tf32 gaussian rows ---------------
__global__ void edge_pre_kernel(const float* __restrict__ pos, const int* __restrict__ eidx) {
    int e = blockIdx.x * blockDim.x + threadIdx.x;
    if (e >= NE_PAD) return;
    bool valid = e < NE;
    float dist = 0.0f;
    if (valid) {
        int r = eidx[e], c = eidx[NE + e];
        float dx = pos[3 * r] - pos[3 * c];
        float dy = pos[3 * r + 1] - pos[3 * c + 1];
        float dz = pos[3 * r + 2] - pos[3 * c + 2];
        dist = sqrtf(dx * dx + dy * dy + dz * dz);
        g_C[e] = 0.5f * (cosf(dist * 0.31415926535897931f) + 1.0f);
    }
    const float delta = 10.0f / 49.0f;
    const float coeff = -0.5f / (delta * delta);
    float* row = g_demb + (size_t)e * KG;
    #pragma unroll
    for (int k = 0; k < KG; k++) {
        float d = dist - (float)k * delta;
        float v = (valid && k < NGAUSS) ? __expf(coeff * d * d) : 0.0f;
        row[k] = __uint_as_float(f2tf32(v));
    }
}

// ---------------- prep: tf32-round edge weights into padded [k][n] ----------
__global__ void prep_w_kernel(const float* __restrict__ mW1, const float* __restrict__ mW2) {
    int idx = blockIdx.x * blockDim.x + threadIdx.x;
    if (idx < NLAY * KG * FC) {
        int l = idx / (KG * FC), rem = idx % (KG * FC);
        int k = rem / FC, n = rem % FC;
        float v = (k < NGAUSS) ? mW1[(l * NGAUSS + k) * FC + n] : 0.0f;
        g_W1t[idx] = __uint_as_float(f2tf32(v));
    }
    if (idx < NLAY * FC * FC) {
        g_W2t[idx] = __uint_as_float(f2tf32(mW2[idx]));
    }
}

__global__ void zero_agg_kernel() {
    for (int i = blockIdx.x * blockDim.x + threadIdx.x; i < NN * HC; i += gridDim.x * blockDim.x)
        g_agg[i] = 0.0f;
}
__global__ void zero_out_kernel(float* __restrict__ out) {
    if (threadIdx.x < NGR) out[threadIdx.x] = 0.0f;
}

// ---------------- fused edge kernel (mma.sync tf32) -------------------------
#define OFF_SW1 0
#define OFF_SW2 (OFF_SW1 + KG * SB)
#define OFF_SD  (OFF_SW2 + FC * SB)
#define OFF_STT (OFF_SD + 128 * SA)
#define OFF_SB1 (OFF_STT + 128 * ST)
#define OFF_SB2 (OFF_SB1 + FC)
#define EDGE_SMEM_F (OFF_SB2 + FC)

__global__ void __launch_bounds__(256, 1)
edge_layer_wmma(const float* __restrict__ b1, const float* __restrict__ b2,
                const int* __restrict__ eidx, int l)
{
    extern __shared__ float s[];
    float* sW1 = s + OFF_SW1;
    float* sW2 = s + OFF_SW2;
    float* sD  = s + OFF_SD;
    float* sT  = s + OFF_STT;
    float* sB1 = s + OFF_SB1;
    float* sB2 = s + OFF_SB2;

    int tid = threadIdx.x;
    int wid = tid >> 5, lane = tid & 31;
    int g = lane >> 2, r = lane & 3;
    int wm = wid & 3, wn = wid >> 2;

    {
        const float* w1 = g_W1t + (size_t)l * KG * FC;
        const float* w2 = g_W2t + (size_t)l * FC * FC;
        for (int i = tid; i < KG * FC; i += 256) sW1[(i >> 7) * SB + (i & 127)] = w1[i];
        for (int i = tid; i < FC * FC; i += 256) sW2[(i >> 7) * SB + (i & 127)] = w2[i];
        for (int i = tid; i < FC; i += 256) { sB1[i] = b1[i]; sB2[i] = b2[i]; }
    }
    __syncthreads();

    for (int t = blockIdx.x; t < NE_TILES; t += gridDim.x) {
        __syncthreads();
        {
            const float* src = g_demb + (size_t)t * 128 * KG;
            #pragma unroll 7
            for (int i = tid; i < 128 * KG; i += 256) {
                int row = i / KG, k = i - row * KG;
                sD[row * SA + k] = src[i];
            }
        }
        __syncthreads();

        // GEMM1: [128,56] @ [56,128]
        float c1[2][8][4];
        #pragma unroll
        for (int im = 0; im < 2; im++)
            #pragma unroll
            for (int jn = 0; jn < 8; jn++)
                #pragma unroll
                for (int q = 0; q < 4; q++) c1[im][jn][q] = 0.0f;

        #pragma unroll
        for (int kk = 0; kk < KG / 8; kk++) {
            uint32_t a[2][4];
            #pragma unroll
            for (int im = 0; im < 2; im++) {
                int rb = wm * 32 + im * 16 + g;
                int kb = kk * 8 + r;
                a[im][0] = __float_as_uint(sD[rb * SA + kb]);
                a[im][1] = __float_as_uint(sD[(rb + 8) * SA + kb]);
                a[im][2] = __float_as_uint(sD[rb * SA + kb + 4]);
                a[im][3] = __float_as_uint(sD[(rb + 8) * SA + kb + 4]);
            }
            #pragma unroll
            for (int jn = 0; jn < 8; jn++) {
                int nb = wn * 64 + jn * 8 + g;
                uint32_t b0 = __float_as_uint(sW1[(kk * 8 + r) * SB + nb]);
                uint32_t bv = __float_as_uint(sW1[(kk * 8 + 4 + r) * SB + nb]);
                mma8(c1[0][jn], a[0], b0, bv);
                mma8(c1[1][jn], a[1], b0, bv);
            }
        }

        #pragma unroll
        for (int im = 0; im < 2; im++) {
            int rb = wm * 32 + im * 16 + g;
            #pragma unroll
            for (int jn = 0; jn < 8; jn++) {
                int col = wn * 64 + jn * 8 + 2 * r;
                float bb0 = sB1[col], bb1 = sB1[col + 1];
                float2 lo, hi;
                lo.x = __uint_as_float(f2tf32(ssp_fast(c1[im][jn][0] + bb0)));
                lo.y = __uint_as_float(f2tf32(ssp_fast(c1[im][jn][1] + bb1)));
                hi.x = __uint_as_float(f2tf32(ssp_fast(c1[im][jn][2] + bb0)));
                hi.y = __uint_as_float(f2tf32(ssp_fast(c1[im][jn][3] + bb1)));
                *(float2*)(sT + rb * ST + col) = lo;
                *(float2*)(sT + (rb + 8) * ST + col) = hi;
            }
        }
        __syncthreads();

        // GEMM2: [128,128] @ [128,128]
        float c2[2][8][4];
        #pragma unroll
        for (int im = 0; im < 2; im++)
            #pragma unroll
            for (int jn = 0; jn < 8; jn++)
                #pragma unroll
                for (int q = 0; q < 4; q++) c2[im][jn][q] = 0.0f;

        #pragma unroll 4
        for (int kk = 0; kk < FC / 8; kk++) {
            uint32_t a[2][4];
            #pragma unroll
            for (int im = 0; im < 2; im++) {
                int rb = wm * 32 + im * 16 + g;
                int kb = kk * 8 + r;
                a[im][0] = __float_as_uint(sT[rb * ST + kb]);
                a[im][1] = __float_as_uint(sT[(rb + 8) * ST + kb]);
                a[im][2] = __float_as_uint(sT[rb * ST + kb + 4]);
                a[im][3] = __float_as_uint(sT[(rb + 8) * ST + kb + 4]);
            }
            #pragma unroll
            for (int jn = 0; jn < 8; jn++) {
                int nb = wn * 64 + jn * 8 + g;
                uint32_t b0 = __float_as_uint(sW2[(kk * 8 + r) * SB + nb]);
                uint32_t bv = __float_as_uint(sW2[(kk * 8 + 4 + r) * SB + nb]);
                mma8(c2[0][jn], a[0], b0, bv);
                mma8(c2[1][jn], a[1], b0, bv);
            }
        }

        // epilogue
        #pragma unroll
        for (int q = 0; q < 4; q++) {
            int im = q >> 1, hi = q & 1;
            int row = wm * 32 + im * 16 + hi * 8 + g;
            int e = t * 128 + row;
            if (e >= NE) continue;
            float Ce = g_C[e];
            int rj = eidx[e];
            int ci = eidx[NE + e];
            const float* xr = g_x + (size_t)rj * HC;
            float* ap = g_agg + (size_t)ci * HC;
            #pragma unroll
            for (int jn = 0; jn < 8; jn++) {
                int col = wn * 64 + jn * 8 + 2 * r;
                float w0 = (c2[im][jn][hi * 2 + 0] + sB2[col]) * Ce;
                float w1 = (c2[im][jn][hi * 2 + 1] + sB2[col + 1]) * Ce;
                float2 xv = *(const float2*)(xr + col);
                red2(ap + col, w0 * xv.x, w1 * xv.y);
            }
        }
    }
}

// ---------------- node GEMM on tensor cores (mma.sync tf32) -----------------
// mode 0: g_x   = g_v   @ W
// mode 1: g_tmp = ssp(g_agg @ W + b)
// mode 2: g_v   = g_v + g_tmp @ W + b
#define NODE_SMEM_F (2 * 128 * SB + FC)

__global__ void __launch_bounds__(256, 1)
node_mma_kernel(const float* __restrict__ W, const float* __restrict__ bias, int mode)
{
    extern __shared__ float s[];
    float* sW = s;                    // [128][SB]
    float* sX = s + 128 * SB;         // [128][SB]
    float* sBias = s + 2 * 128 * SB;  // [128]

    const float* X = (mode == 0) ? g_v : (mode == 1) ? g_agg : g_tmp;
    float*       Y = (mode == 0) ? g_x : (mode == 1) ? g_tmp : g_v;

    int tid = threadIdx.x;
    int wid = tid >> 5, lane = tid & 31;
    int g = lane >> 2, r = lane & 3;
    int wm = wid & 3, wn = wid >> 2;
    int n0 = blockIdx.x * NT;

    for (int i = tid; i < HC * FC; i += 256)
        sW[(i >> 7) * SB + (i & 127)] = __uint_as_float(f2tf32(W[i]));
    for (int i = tid; i < NT * HC; i += 256) {
        int rr = i >> 7, c = i & 127;
        int n = n0 + rr;
        sX[rr * SB + c] = (n < NN) ? __uint_as_float(f2tf32(X[(size_t)n * HC + c])) : 0.0f;
    }
    if (mode != 0 && tid < FC) sBias[tid] = bias[tid];
    __syncthreads();

    float c2[2][8][4];
    #pragma unroll
    for (int im = 0; im < 2; im++)
        #pragma unroll
        for (int jn = 0; jn < 8; jn++)
            #pragma unroll
            for (int q = 0; q < 4; q++) c2[im][jn][q] = 0.0f;

    #pragma unroll 4
    for (int kk = 0; kk < FC / 8; kk++) {
        uint32_t a[2][4];
        #pragma unroll
        for (int im = 0; im < 2; im++) {
            int rb = wm * 32 + im * 16 + g;
            int kb = kk * 8 + r;
            a[im][0] = __float_as_uint(sX[rb * SB + kb]);
            a[im][1] = __float_as_uint(sX[(rb + 8) * SB + kb]);
            a[im][2] = __float_as_uint(sX[rb * SB + kb + 4]);
            a[im][3] = __float_as_uint(sX[(rb + 8) * SB + kb + 4]);
        }
        #pragma unroll
        for (int jn = 0; jn < 8; jn++) {
            int nb = wn * 64 + jn * 8 + g;
            uint32_t b0 = __float_as_uint(sW[(kk * 8 + r) * SB + nb]);
            uint32_t bv = __float_as_uint(sW[(kk * 8 + 4 + r) * SB + nb]);
            mma8(c2[0][jn], a[0], b0, bv);
            mma8(c2[1][jn], a[1], b0, bv);
        }
    }

    #pragma unroll
    for (int q = 0; q < 4; q++) {
        int im = q >> 1, hi = q & 1;
        int row = wm * 32 + im * 16 + hi * 8 + g;
        int n = n0 + row;
        if (n >= NN) continue;
        float* yp = Y + (size_t)n * HC;
        #pragma unroll
        for (int jn = 0; jn < 8; jn++) {
            int col = wn * 64 + jn * 8 + 2 * r;
            float w0 = c2[im][jn][hi * 2 + 0];
            float w1 = c2[im][jn][hi * 2 + 1];
            float2 o;
            if (mode == 0) {
                o.x = w0; o.y = w1;
            } else if (mode == 1) {
                o.x = ssp_f(w0 + sBias[col]);
                o.y = ssp_f(w1 + sBias[col + 1]);
            } else {
                float2 old = *(const float2*)(yp + col);
                o.x = old.x + w0 + sBias[col];
                o.y = old.y + w1 + sBias[col + 1];
            }
            *(float2*)(yp + col) = o;
        }
    }
}

// ---------------- readout ---------------------------------------------------
__global__ void readout_kernel(const int* __restrict__ batch,
                               const float* __restrict__ uW1, const float* __restrict__ ub1,
                               const float* __restrict__ uW2, const float* __restrict__ ub2,
                               float* __restrict__ out)
{
    __shared__ float sv[8][HC];
    int tid = threadIdx.x;
    int w = tid >> 5, l = tid & 31;
    int n0 = blockIdx.x * 8;
    for (int i = tid; i < 8 * HC; i += 256) {
        int n = n0 + (i >> 7);
        sv[i >> 7][i & 127] = (n < NN) ? g_v[(size_t)n * HC + (i & 127)] : 0.0f;
    }
    __syncthreads();
    int n = n0 + w;
    if (n >= NN) return;
    float a0 = 0.0f, a1 = 0.0f;
    #pragma unroll 8
    for (int h = 0; h < HC; h++) {
        float vv = sv[w][h];
        a0 += vv * uW1[h * 64 + l];
        a1 += vv * uW1[h * 64 + l + 32];
    }
    float h0 = ssp_f(a0 + ub1[l]);
    float h1 = ssp_f(a1 + ub1[l + 32]);
    float p = h0 * uW2[l] + h1 * uW2[l + 32];
    #pragma unroll
    for (int o = 16; o; o >>= 1) p += __shfl_down_sync(0xffffffffu, p, o);
    if (l == 0) atomicAdd(&out[batch[n]], p + ub2[0]);
}

// ---------------- launch ----------------------------------------------------
extern "C" void kernel_launch(void* const* d_in, const int* in_sizes, int n_in,
                              void* d_out, int out_size)
{
    const int*   z     = (const int*)d_in[0];
    const float* pos   = (const float*)d_in[1];
    const int*   batch = (const int*)d_in[2];
    const int*   eidx  = (const int*)d_in[3];
    const float* emb   = (const float*)d_in[4];
    const float* lin_W = (const float*)d_in[5];
    const float* mW1   = (const float*)d_in[6];
    const float* mb1   = (const float*)d_in[7];
    const float* mW2   = (const float*)d_in[8];
    const float* mb2   = (const float*)d_in[9];
    const float* vW1   = (const float*)d_in[10];
    const float* vb1   = (const float*)d_in[11];
    const float* vW2   = (const float*)d_in[12];
    const float* vb2   = (const float*)d_in[13];
    const float* uW1   = (const float*)d_in[14];
    const float* ub1   = (const float*)d_in[15];
    const float* uW2   = (const float*)d_in[16];
    const float* ub2   = (const float*)d_in[17];
    float* out = (float*)d_out;

    const int EDGE_SMEM = EDGE_SMEM_F * (int)sizeof(float);
    const int NODE_SMEM = NODE_SMEM_F * (int)sizeof(float);
    cudaFuncSetAttribute(edge_layer_wmma, cudaFuncAttributeMaxDynamicSharedMemorySize, EDGE_SMEM);
    cudaFuncSetAttribute(node_mma_kernel, cudaFuncAttributeMaxDynamicSharedMemorySize, NODE_SMEM);

    init_v_kernel<<<(NN * HC + 255) / 256, 256>>>(z, emb);
    edge_pre_kernel<<<(NE_PAD + 255) / 256, 256>>>(pos, eidx);
    prep_w_kernel<<<(NLAY * FC * FC + 255) / 256, 256>>>(mW1, mW2);

    const int NODE_GRID = (NN + NT - 1) / NT;   // 391
    for (int l = 0; l < NLAY; l++) {
        node_mma_kernel<<<NODE_GRID, 256, NODE_SMEM>>>(lin_W + (size_t)l * HC * FC, nullptr, 0);
        zero_agg_kernel<<<1024, 256>>>();
        edge_layer_wmma<<<148, 256, EDGE_SMEM>>>(mb1 + (size_t)l * FC, mb2 + (size_t)l * FC, eidx, l);
        node_mma_kernel<<<NODE_GRID, 256, NODE_SMEM>>>(vW1 + (size_t)l * FC * HC, vb1 + (size_t)l * HC, 1);
        node_mma_kernel<<<NODE_GRID, 256, NODE_SMEM>>>(vW2 + (size_t)l * HC * HC, vb2 + (size_t)l * HC, 2);
    }

    zero_out_kernel<<<1, 64>>>(out);
    readout_kernel<<<(NN + 7) / 8, 256>>>(batch, uW1, ub1, uW2, ub2, out);
    (void)in_sizes; (void)n_in; (void)out_size;
}

// round 5
// speedup vs baseline: 7.4251x; 3.6465x over previous
#include <cuda_runtime.h>
#include <math.h>
#include <stdint.h>

#define NN 50000
#define NE 625000
#define NGR 64
#define HC 128
#define FC 128
#define NGAUSS 50
#define KG 56                         // gaussian K padded to 56 (mult of 8)
#define NLAY 6
#define NT 128                        // node tile rows

#define NLUT 16384
#define DMAX 20.0f
#define LUT_STEP (DMAX / (float)NLUT)
#define INV_STEP ((float)NLUT / DMAX)

// smem strides (floats) — conflict-free fragment loads
#define SA 60     // sD stride
#define SB 132    // weight / activation stride
#define ST 132    // sT stride

// ---------------- scratch (device globals; no allocation allowed) ----------
__device__ float g_dist[NE];
__device__ float g_v[NN * HC];
__device__ float g_x[NN * HC];
__device__ float g_agg[NN * HC];
__device__ float g_tmp[NN * HC];
__device__ float g_W1t[NLAY * KG * FC];          // [l][k][n] tf32, zero-padded
__device__ float g_W2t[NLAY * FC * FC];          // [l][k][n] tf32
__device__ float g_lut[(size_t)NLAY * NLUT * HC]; // per-layer filter LUT (C folded in)

// ---------------- helpers ---------------------------------------------------
__device__ __forceinline__ uint32_t f2tf32(float x) {
    uint32_t r;
    asm("cvt.rna.tf32.f32 %0, %1;" : "=r"(r) : "f"(x));
    return r;
}
__device__ __forceinline__ void mma8(float* c, const uint32_t* a, uint32_t b0, uint32_t b1) {
    asm volatile("mma.sync.aligned.m16n8k8.row.col.f32.tf32.tf32.f32 "
                 "{%0,%1,%2,%3},{%4,%5,%6,%7},{%8,%9},{%0,%1,%2,%3};"
                 : "+f"(c[0]), "+f"(c[1]), "+f"(c[2]), "+f"(c[3])
                 : "r"(a[0]), "r"(a[1]), "r"(a[2]), "r"(a[3]), "r"(b0), "r"(b1));
}
__device__ __forceinline__ void red4(float* p, float a, float b, float c, float d) {
    asm volatile("red.global.add.v4.f32 [%0], {%1,%2,%3,%4};" :: "l"(p), "f"(a), "f"(b), "f"(c), "f"(d) : "memory");
}
__device__ __forceinline__ float ssp_f(float x) {
    return fmaxf(x, 0.0f) + log1pf(expf(-fabsf(x))) - 0.69314718055994531f;
}

// ---------------- init: v = emb_table[z] -----------------------------------
__global__ void init_v_kernel(const int* __restrict__ z, const float* __restrict__ emb) {
    int idx = blockIdx.x * blockDim.x + threadIdx.x;
    if (idx < NN * HC) g_v[idx] = emb[z[idx >> 7] * HC + (idx & 127)];
}

// ---------------- per-edge precompute: dist only ----------------------------
__global__ void edge_pre_kernel(const float* __restrict__ pos, const int* __restrict__ eidx) {
    int e = blockIdx.x * blockDim.x + threadIdx.x;
    if (e >= NE) return;
    int r = eidx[e], c = eidx[NE + e];
    float dx = pos[3 * r] - pos[3 * c];
    float dy = pos[3 * r + 1] - pos[3 * c + 1];
    float dz = pos[3 * r + 2] - pos[3 * c + 2];
    g_dist[e] = sqrtf(dx * dx + dy * dy + dz * dz);
}

// ---------------- prep: tf32-round edge weights into padded [k][n] ----------
__global__ void prep_w_kernel(const float* __restrict__ mW1, const float* __restrict__ mW2) {
    int idx = blockIdx.x * blockDim.x + threadIdx.x;
    if (idx < NLAY * KG * FC) {
        int l = idx / (KG * FC), rem = idx % (KG * FC);
        int k = rem / FC, n = rem % FC;
        float v = (k < NGAUSS) ? mW1[(l * NGAUSS + k) * FC + n] : 0.0f;
        g_W1t[idx] = __uint_as_float(f2tf32(v));
    }
    if (idx < NLAY * FC * FC) {
        g_W2t[idx] = __uint_as_float(f2tf32(mW2[idx]));
    }
}

__global__ void zero_out_kernel(float* __restrict__ out) {
    if (threadIdx.x < NGR) out[threadIdx.x] = 0.0f;
}

// ---------------- LUT generation (tf32 mma, one tile = 128 dist samples) ----
#define OFF_SW1 0
#define OFF_SW2 (OFF_SW1 + KG * SB)
#define OFF_SD  (OFF_SW2 + FC * SB)
#define OFF_STT (OFF_SD + 128 * SA)
#define OFF_SB1 (OFF_STT + 128 * ST)
#define OFF_SB2 (OFF_SB1 + FC)
#define EDGE_SMEM_F (OFF_SB2 + FC)

__global__ void __launch_bounds__(256, 1)
lut_gen_kernel(const float* __restrict__ mb1, const float* __restrict__ mb2)
{
    extern __shared__ float s[];
    float* sW1 = s + OFF_SW1;
    float* sW2 = s + OFF_SW2;
    float* sD  = s + OFF_SD;
    float* sT  = s + OFF_STT;
    float* sB1 = s + OFF_SB1;
    float* sB2 = s + OFF_SB2;

    int tid = threadIdx.x;
    int wid = tid >> 5, lane = tid & 31;
    int g = lane >> 2, r = lane & 3;
    int wm = wid & 3, wn = wid >> 2;
    int t = blockIdx.x;          // 0..127
    int l = blockIdx.y;          // layer

    {
        const float* w1 = g_W1t + (size_t)l * KG * FC;
        const float* w2 = g_W2t + (size_t)l * FC * FC;
        const float* b1 = mb1 + (size_t)l * FC;
        const float* b2 = mb2 + (size_t)l * FC;
        for (int i = tid; i < KG * FC; i += 256) sW1[(i >> 7) * SB + (i & 127)] = w1[i];
        for (int i = tid; i < FC * FC; i += 256) sW2[(i >> 7) * SB + (i & 127)] = w2[i];
        for (int i = tid; i < FC; i += 256) { sB1[i] = b1[i]; sB2[i] = b2[i]; }
    }
    // gaussian rows for the 128 sample distances of this tile
    {
        const float delta = 10.0f / 49.0f;
        const float coeff = -0.5f / (delta * delta);
        for (int i = tid; i < 128 * KG; i += 256) {
            int row = i / KG, k = i - row * KG;
            float d = (float)(t * 128 + row) * LUT_STEP;
            float dd = d - (float)k * delta;
            float v = (k < NGAUSS) ? expf(coeff * dd * dd) : 0.0f;
            sD[row * SA + k] = __uint_as_float(f2tf32(v));
        }
    }
    __syncthreads();

    // GEMM1: [128,56] @ [56,128]
    float c1[2][8][4];
    #pragma unroll
    for (int im = 0; im < 2; im++)
        #pragma unroll
        for (int jn = 0; jn < 8; jn++)
            #pragma unroll
            for (int q = 0; q < 4; q++) c1[im][jn][q] = 0.0f;

    #pragma unroll
    for (int kk = 0; kk < KG / 8; kk++) {
        uint32_t a[2][4];
        #pragma unroll
        for (int im = 0; im < 2; im++) {
            int rb = wm * 32 + im * 16 + g;
            int kb = kk * 8 + r;
            a[im][0] = __float_as_uint(sD[rb * SA + kb]);
            a[im][1] = __float_as_uint(sD[(rb + 8) * SA + kb]);
            a[im][2] = __float_as_uint(sD[rb * SA + kb + 4]);
            a[im][3] = __float_as_uint(sD[(rb + 8) * SA + kb + 4]);
        }
        #pragma unroll
        for (int jn = 0; jn < 8; jn++) {
            int nb = wn * 64 + jn * 8 + g;
            uint32_t b0 = __float_as_uint(sW1[(kk * 8 + r) * SB + nb]);
            uint32_t bv = __float_as_uint(sW1[(kk * 8 + 4 + r) * SB + nb]);
            mma8(c1[0][jn], a[0], b0, bv);
            mma8(c1[1][jn], a[1], b0, bv);
        }
    }

    #pragma unroll
    for (int im = 0; im < 2; im++) {
        int rb = wm * 32 + im * 16 + g;
        #pragma unroll
        for (int jn = 0; jn < 8; jn++) {
            int col = wn * 64 + jn * 8 + 2 * r;
            float bb0 = sB1[col], bb1 = sB1[col + 1];
            float2 lo, hi;
            lo.x = __uint_as_float(f2tf32(ssp_f(c1[im][jn][0] + bb0)));
            lo.y = __uint_as_float(f2tf32(ssp_f(c1[im][jn][1] + bb1)));
            hi.x = __uint_as_float(f2tf32(ssp_f(c1[im][jn][2] + bb0)));
            hi.y = __uint_as_float(f2tf32(ssp_f(c1[im][jn][3] + bb1)));
            *(float2*)(sT + rb * ST + col) = lo;
            *(float2*)(sT + (rb + 8) * ST + col) = hi;
        }
    }
    __syncthreads();

    // GEMM2: [128,128] @ [128,128]
    float c2[2][8][4];
    #pragma unroll
    for (int im = 0; im < 2; im++)
        #pragma unroll
        for (int jn = 0; jn < 8; jn++)
            #pragma unroll
            for (int q = 0; q < 4; q++) c2[im][jn][q] = 0.0f;

    #pragma unroll 4
    for (int kk = 0; kk < FC / 8; kk++) {
        uint32_t a[2][4];
        #pragma unroll
        for (int im = 0; im < 2; im++) {
            int rb = wm * 32 + im * 16 + g;
            int kb = kk * 8 + r;
            a[im][0] = __float_as_uint(sT[rb * ST + kb]);
            a[im][1] = __float_as_uint(sT[(rb + 8) * ST + kb]);
            a[im][2] = __float_as_uint(sT[rb * ST + kb + 4]);
            a[im][3] = __float_as_uint(sT[(rb + 8) * ST + kb + 4]);
        }
        #pragma unroll
        for (int jn = 0; jn < 8; jn++) {
            int nb = wn * 64 + jn * 8 + g;
            uint32_t b0 = __float_as_uint(sW2[(kk * 8 + r) * SB + nb]);
            uint32_t bv = __float_as_uint(sW2[(kk * 8 + 4 + r) * SB + nb]);
            mma8(c2[0][jn], a[0], b0, bv);
            mma8(c2[1][jn], a[1], b0, bv);
        }
    }

    // epilogue: + b2, * C(d), write LUT row
    float* lutL = g_lut + (size_t)l * NLUT * HC;
    #pragma unroll
    for (int q = 0; q < 4; q++) {
        int im = q >> 1, hi = q & 1;
        int row = wm * 32 + im * 16 + hi * 8 + g;
        int idx = t * 128 + row;
        float d = (float)idx * LUT_STEP;
        float Ce = 0.5f * (cosf(d * 0.31415926535897931f) + 1.0f);
        float* lp = lutL + (size_t)idx * HC;
        #pragma unroll
        for (int jn = 0; jn < 8; jn++) {
            int col = wn * 64 + jn * 8 + 2 * r;
            float2 o;
            o.x = (c2[im][jn][hi * 2 + 0] + sB2[col]) * Ce;
            o.y = (c2[im][jn][hi * 2 + 1] + sB2[col + 1]) * Ce;
            *(float2*)(lp + col) = o;
        }
    }
}

// ---------------- edge apply: lerp(LUT) * x[row] -> red agg[col] ------------
__global__ void __launch_bounds__(256)
edge_apply_kernel(const int* __restrict__ eidx, const float* __restrict__ lut)
{
    int lane = threadIdx.x & 31;
    int wg = blockIdx.x * 8 + (threadIdx.x >> 5);
    int nw = gridDim.x * 8;
    for (int e = wg; e < NE; e += nw) {
        float dist = g_dist[e];
        int rj = eidx[e];
        int ci = eidx[NE + e];
        float u = dist * INV_STEP;
        int i0 = (int)u;
        i0 = (i0 > NLUT - 2) ? (NLUT - 2) : i0;
        float f = u - (float)i0;
        const float4* l0 = (const float4*)(lut + (size_t)i0 * HC) + lane;
        float4 a = l0[0];
        float4 b = l0[32];                 // next LUT row
        float4 x = ((const float4*)(g_x + (size_t)rj * HC))[lane];
        float w0 = fmaf(f, b.x - a.x, a.x) * x.x;
        float w1 = fmaf(f, b.y - a.y, a.y) * x.y;
        float w2 = fmaf(f, b.z - a.z, a.z) * x.z;
        float w3 = fmaf(f, b.w - a.w, a.w) * x.w;
        red4(g_agg + (size_t)ci * HC + lane * 4, w0, w1, w2, w3);
    }
}

// ---------------- node GEMM on tensor cores (512 thr, 16 warps) -------------
// mode 0: g_x   = g_v   @ W              (also zeroes g_agg rows)
// mode 1: g_tmp = ssp(g_agg @ W + b)
// mode 2: g_v   = g_v + g_tmp @ W + b
#define NODE_SMEM_F (2 * 128 * SB + FC)

__global__ void __launch_bounds__(512, 1)
node_mma_kernel(const float* __restrict__ W, const float* __restrict__ bias, int mode)
{
    extern __shared__ float s[];
    float* sW = s;                    // [128][SB]
    float* sX = s + 128 * SB;         // [128][SB]
    float* sBias = s + 2 * 128 * SB;  // [128]

    const float* X = (mode == 0) ? g_v : (mode == 1) ? g_agg : g_tmp;
    float*       Y = (mode == 0) ? g_x : (mode == 1) ? g_tmp : g_v;

    int tid = threadIdx.x;
    int wid = tid >> 5, lane = tid & 31;
    int g = lane >> 2, r = lane & 3;
    int wm = wid & 3, wn = wid >> 2;   // 4 x 4 warp grid, 32x32 tiles
    int n0 = blockIdx.x * NT;

    for (int i = tid; i < HC * FC; i += 512)
        sW[(i >> 7) * SB + (i & 127)] = __uint_as_float(f2tf32(W[i]));
    for (int i = tid; i < NT * HC; i += 512) {
        int rr = i >> 7, c = i & 127;
        int n = n0 + rr;
        sX[rr * SB + c] = (n < NN) ? __uint_as_float(f2tf32(X[(size_t)n * HC + c])) : 0.0f;
    }
    if (mode == 0) {
        // zero agg rows for this tile (ready before edge_apply launches)
        for (int i = tid; i < NT * HC; i += 512) {
            int n = n0 + (i >> 7);
            if (n < NN) g_agg[(size_t)n * HC + (i & 127)] = 0.0f;
        }
    } else if (tid < FC) {
        sBias[tid] = bias[tid];
    }
    __syncthreads();

    float c2[2][4][4];
    #pragma unroll
    for (int im = 0; im < 2; im++)
        #pragma unroll
        for (int jn = 0; jn < 4; jn++)
            #pragma unroll
            for (int q = 0; q < 4; q++) c2[im][jn][q] = 0.0f;

    #pragma unroll 4
    for (int kk = 0; kk < FC / 8; kk++) {
        uint32_t a[2][4];
        #pragma unroll
        for (int im = 0; im < 2; im++) {
            int rb = wm * 32 + im * 16 + g;
            int kb = kk * 8 + r;
            a[im][0] = __float_as_uint(sX[rb * SB + kb]);
            a[im][1] = __float_as_uint(sX[(rb + 8) * SB + kb]);
            a[im][2] = __float_as_uint(sX[rb * SB + kb + 4]);
            a[im][3] = __float_as_uint(sX[(rb + 8) * SB + kb + 4]);
        }
        #pragma unroll
        for (int jn = 0; jn < 4; jn++) {
            int nb = wn * 32 + jn * 8 + g;
            uint32_t b0 = __float_as_uint(sW[(kk * 8 + r) * SB + nb]);
            uint32_t bv = __float_as_uint(sW[(kk * 8 + 4 + r) * SB + nb]);
            mma8(c2[0][jn], a[0], b0, bv);
            mma8(c2[1][jn], a[1], b0, bv);
        }
    }

    #pragma unroll
    for (int q = 0; q < 4; q++) {
        int im = q >> 1, hi = q & 1;
        int row = wm * 32 + im * 16 + hi * 8 + g;
        int n = n0 + row;
        if (n >= NN) continue;
        float* yp = Y + (size_t)n * HC;
        #pragma unroll
        for (int jn = 0; jn < 4; jn++) {
            int col = wn * 32 + jn * 8 + 2 * r;
            float w0 = c2[im][jn][hi * 2 + 0];
            float w1 = c2[im][jn][hi * 2 + 1];
            float2 o;
            if (mode == 0) {
                o.x = w0; o.y = w1;
            } else if (mode == 1) {
                o.x = ssp_f(w0 + sBias[col]);
                o.y = ssp_f(w1 + sBias[col + 1]);
            } else {
                float2 old = *(const float2*)(yp + col);
                o.x = old.x + w0 + sBias[col];
                o.y = old.y + w1 + sBias[col + 1];
            }
            *(float2*)(yp + col) = o;
        }
    }
}

// ---------------- readout ---------------------------------------------------
__global__ void readout_kernel(const int* __restrict__ batch,
                               const float* __restrict__ uW1, const float* __restrict__ ub1,
                               const float* __restrict__ uW2, const float* __restrict__ ub2,
                               float* __restrict__ out)
{
    __shared__ float sv[8][HC];
    int tid = threadIdx.x;
    int w = tid >> 5, l = tid & 31;
    int n0 = blockIdx.x * 8;
    for (int i = tid; i < 8 * HC; i += 256) {
        int n = n0 + (i >> 7);
        sv[i >> 7][i & 127] = (n < NN) ? g_v[(size_t)n * HC + (i & 127)] : 0.0f;
    }
    __syncthreads();
    int n = n0 + w;
    if (n >= NN) return;
    float a0 = 0.0f, a1 = 0.0f;
    #pragma unroll 8
    for (int h = 0; h < HC; h++) {
        float vv = sv[w][h];
        a0 += vv * uW1[h * 64 + l];
        a1 += vv * uW1[h * 64 + l + 32];
    }
    float h0 = ssp_f(a0 + ub1[l]);
    float h1 = ssp_f(a1 + ub1[l + 32]);
    float p = h0 * uW2[l] + h1 * uW2[l + 32];
    #pragma unroll
    for (int o = 16; o; o >>= 1) p += __shfl_down_sync(0xffffffffu, p, o);
    if (l == 0) atomicAdd(&out[batch[n]], p + ub2[0]);
}

// ---------------- launch ----------------------------------------------------
extern "C" void kernel_launch(void* const* d_in, const int* in_sizes, int n_in,
                              void* d_out, int out_size)
{
    const int*   z     = (const int*)d_in[0];
    const float* pos   = (const float*)d_in[1];
    const int*   batch = (const int*)d_in[2];
    const int*   eidx  = (const int*)d_in[3];
    const float* emb   = (const float*)d_in[4];
    const float* lin_W = (const float*)d_in[5];
    const float* mW1   = (const float*)d_in[6];
    const float* mb1   = (const float*)d_in[7];
    const float* mW2   = (const float*)d_in[8];
    const float* mb2   = (const float*)d_in[9];
    const float* vW1   = (const float*)d_in[10];
    const float* vb1   = (const float*)d_in[11];
    const float* vW2   = (const float*)d_in[12];
    const float* vb2   = (const float*)d_in[13];
    const float* uW1   = (const float*)d_in[14];
    const float* ub1   = (const float*)d_in[15];
    const float* uW2   = (const float*)d_in[16];
    const float* ub2   = (const float*)d_in[17];
    float* out = (float*)d_out;

    const int EDGE_SMEM = EDGE_SMEM_F * (int)sizeof(float);
    const int NODE_SMEM = NODE_SMEM_F * (int)sizeof(float);
    cudaFuncSetAttribute(lut_gen_kernel, cudaFuncAttributeMaxDynamicSharedMemorySize, EDGE_SMEM);
    cudaFuncSetAttribute(node_mma_kernel, cudaFuncAttributeMaxDynamicSharedMemorySize, NODE_SMEM);

    init_v_kernel<<<(NN * HC + 255) / 256, 256>>>(z, emb);
    edge_pre_kernel<<<(NE + 255) / 256, 256>>>(pos, eidx);
    prep_w_kernel<<<(NLAY * FC * FC + 255) / 256, 256>>>(mW1, mW2);
    lut_gen_kernel<<<dim3(NLUT / 128, NLAY), 256, EDGE_SMEM>>>(mb1, mb2);

    const int NODE_GRID = (NN + NT - 1) / NT;   // 391
    float* lutDev;
    cudaGetSymbolAddress((void**)&lutDev, g_lut);
    for (int l = 0; l < NLAY; l++) {
        node_mma_kernel<<<NODE_GRID, 512, NODE_SMEM>>>(lin_W + (size_t)l * HC * FC, nullptr, 0);
        edge_apply_kernel<<<1184, 256>>>(eidx, lutDev + (size_t)l * NLUT * HC);
        node_mma_kernel<<<NODE_GRID, 512, NODE_SMEM>>>(vW1 + (size_t)l * FC * HC, vb1 + (size_t)l * HC, 1);
        node_mma_kernel<<<NODE_GRID, 512, NODE_SMEM>>>(vW2 + (size_t)l * HC * HC, vb2 + (size_t)l * HC, 2);
    }

    zero_out_kernel<<<1, 64>>>(out);
    readout_kernel<<<(NN + 7) / 8, 256>>>(batch, uW1, ub1, uW2, ub2, out);
    (void)in_sizes; (void)n_in; (void)out_size;
}

// round 6
// speedup vs baseline: 9.9246x; 1.3366x over previous
#include <cuda_runtime.h>
#include <math.h>
#include <stdint.h>

#define NN 50000
#define NE 625000
#define NGR 64
#define HC 128
#define FC 128
#define NGAUSS 50
#define KG 56                         // gaussian K padded to 56 (mult of 8)
#define NLAY 6
#define NT 128                        // node tile rows

#define NLUT 8192
#define DMAX 20.0f
#define LUT_STEP (DMAX / (float)NLUT)
#define INV_STEP ((float)NLUT / DMAX)

// smem strides (floats) — conflict-free fragment loads
#define SA 60     // sD stride (lut_gen)
#define SB 132    // weight / activation stride

// ---------------- scratch (device globals; no allocation allowed) ----------
__device__ float g_v[NN * HC];
__device__ float g_x[NN * HC];
__device__ float g_agg[NN * HC];
__device__ float g_W1t[NLAY * KG * FC];           // [l][k][n] tf32, zero-padded
__device__ float g_W2t[NLAY * FC * FC];           // [l][k][n] tf32
__device__ float g_lut[(size_t)NLAY * NLUT * HC]; // per-layer filter LUT (C folded)
// CSR edge structure (by destination node)
__device__ float g_uraw[NE];         // dist * INV_STEP, original edge order
__device__ int   g_cnt[NN];
__device__ int   g_fill[NN];
__device__ int   g_rowstart[NN + 1];
__device__ int   g_esrc[NE];         // source node, CSR order
__device__ float g_eu[NE];           // u, CSR order

// ---------------- helpers ---------------------------------------------------
__device__ __forceinline__ uint32_t f2tf32(float x) {
    uint32_t r;
    asm("cvt.rna.tf32.f32 %0, %1;" : "=r"(r) : "f"(x));
    return r;
}
__device__ __forceinline__ void mma8(float* c, const uint32_t* a, uint32_t b0, uint32_t b1) {
    asm volatile("mma.sync.aligned.m16n8k8.row.col.f32.tf32.tf32.f32 "
                 "{%0,%1,%2,%3},{%4,%5,%6,%7},{%8,%9},{%0,%1,%2,%3};"
                 : "+f"(c[0]), "+f"(c[1]), "+f"(c[2]), "+f"(c[3])
                 : "r"(a[0]), "r"(a[1]), "r"(a[2]), "r"(a[3]), "r"(b0), "r"(b1));
}
__device__ __forceinline__ float ssp_f(float x) {
    return fmaxf(x, 0.0f) + log1pf(expf(-fabsf(x))) - 0.69314718055994531f;
}

// ---------------- init: v = emb_table[z] -----------------------------------
__global__ void init_v_kernel(const int* __restrict__ z, const float* __restrict__ emb) {
    int idx = blockIdx.x * blockDim.x + threadIdx.x;
    if (idx < NN * HC) g_v[idx] = emb[z[idx >> 7] * HC + (idx & 127)];
}

// ---------------- CSR build -------------------------------------------------
__global__ void zero_cnt_kernel() {
    int i = blockIdx.x * blockDim.x + threadIdx.x;
    if (i < NN) { g_cnt[i] = 0; g_fill[i] = 0; }
}

__global__ void edge_pre_kernel(const float* __restrict__ pos, const int* __restrict__ eidx) {
    int e = blockIdx.x * blockDim.x + threadIdx.x;
    if (e >= NE) return;
    int r = eidx[e], c = eidx[NE + e];
    float dx = pos[3 * r] - pos[3 * c];
    float dy = pos[3 * r + 1] - pos[3 * c + 1];
    float dz = pos[3 * r + 2] - pos[3 * c + 2];
    g_uraw[e] = sqrtf(dx * dx + dy * dy + dz * dz) * INV_STEP;
    atomicAdd(&g_cnt[c], 1);
}

#define SCAN_T 1024
#define PER_T 49                       // 1024*49 = 50176 >= NN
__global__ void scan_kernel() {
    __shared__ int ps[SCAN_T];
    int t = threadIdx.x;
    int base = t * PER_T;
    int s = 0;
    for (int i = 0; i < PER_T; i++) {
        int n = base + i;
        if (n < NN) s += g_cnt[n];
    }
    ps[t] = s;
    __syncthreads();
    for (int off = 1; off < SCAN_T; off <<= 1) {
        int v = (t >= off) ? ps[t - off] : 0;
        __syncthreads();
        ps[t] += v;
        __syncthreads();
    }
    int run = ps[t] - s;               // exclusive start of this chunk
    for (int i = 0; i < PER_T; i++) {
        int n = base + i;
        if (n < NN) { g_rowstart[n] = run; run += g_cnt[n]; }
    }
    if (t == SCAN_T - 1) g_rowstart[NN] = ps[SCAN_T - 1];
}

__global__ void scatter_kernel(const int* __restrict__ eidx) {
    int e = blockIdx.x * blockDim.x + threadIdx.x;
    if (e >= NE) return;
    int ci = eidx[NE + e];
    int pos = g_rowstart[ci] + atomicAdd(&g_fill[ci], 1);
    g_esrc[pos] = eidx[e];
    g_eu[pos] = g_uraw[e];
}

// ---------------- prep: tf32-round edge weights into padded [k][n] ----------
__global__ void prep_w_kernel(const float* __restrict__ mW1, const float* __restrict__ mW2) {
    int idx = blockIdx.x * blockDim.x + threadIdx.x;
    if (idx < NLAY * KG * FC) {
        int l = idx / (KG * FC), rem = idx % (KG * FC);
        int k = rem / FC, n = rem % FC;
        float v = (k < NGAUSS) ? mW1[(l * NGAUSS + k) * FC + n] : 0.0f;
        g_W1t[idx] = __uint_as_float(f2tf32(v));
    }
    if (idx < NLAY * FC * FC) {
        g_W2t[idx] = __uint_as_float(f2tf32(mW2[idx]));
    }
}

__global__ void zero_out_kernel(float* __restrict__ out) {
    if (threadIdx.x < NGR) out[threadIdx.x] = 0.0f;
}

// ---------------- LUT generation (tf32 mma, one tile = 128 dist samples) ----
#define OFF_SW1 0
#define OFF_SW2 (OFF_SW1 + KG * SB)
#define OFF_SD  (OFF_SW2 + FC * SB)
#define OFF_STT (OFF_SD + 128 * SA)
#define OFF_SB1 (OFF_STT + 128 * SB)
#define OFF_SB2 (OFF_SB1 + FC)
#define LUT_SMEM_F (OFF_SB2 + FC)

__global__ void __launch_bounds__(256, 1)
lut_gen_kernel(const float* __restrict__ mb1, const float* __restrict__ mb2)
{
    extern __shared__ float s[];
    float* sW1 = s + OFF_SW1;
    float* sW2 = s + OFF_SW2;
    float* sD  = s + OFF_SD;
    float* sT  = s + OFF_STT;
    float* sB1 = s + OFF_SB1;
    float* sB2 = s + OFF_SB2;

    int tid = threadIdx.x;
    int wid = tid >> 5, lane = tid & 31;
    int g = lane >> 2, r = lane & 3;
    int wm = wid & 3, wn = wid >> 2;
    int t = blockIdx.x;
    int l = blockIdx.y;

    {
        const float* w1 = g_W1t + (size_t)l * KG * FC;
        const float* w2 = g_W2t + (size_t)l * FC * FC;
        const float* b1 = mb1 + (size_t)l * FC;
        const float* b2 = mb2 + (size_t)l * FC;
        for (int i = tid; i < KG * FC; i += 256) sW1[(i >> 7) * SB + (i & 127)] = w1[i];
        for (int i = tid; i < FC * FC; i += 256) sW2[(i >> 7) * SB + (i & 127)] = w2[i];
        for (int i = tid; i < FC; i += 256) { sB1[i] = b1[i]; sB2[i] = b2[i]; }
    }
    {
        const float delta = 10.0f / 49.0f;
        const float coeff = -0.5f / (delta * delta);
        for (int i = tid; i < 128 * KG; i += 256) {
            int row = i / KG, k = i - row * KG;
            float d = (float)(t * 128 + row) * LUT_STEP;
            float dd = d - (float)k * delta;
            float v = (k < NGAUSS) ? expf(coeff * dd * dd) : 0.0f;
            sD[row * SA + k] = __uint_as_float(f2tf32(v));
        }
    }
    __syncthreads();

    // GEMM1: [128,56] @ [56,128]
    float c1[2][8][4];
    #pragma unroll
    for (int im = 0; im < 2; im++)
        #pragma unroll
        for (int jn = 0; jn < 8; jn++)
            #pragma unroll
            for (int q = 0; q < 4; q++) c1[im][jn][q] = 0.0f;

    #pragma unroll
    for (int kk = 0; kk < KG / 8; kk++) {
        uint32_t a[2][4];
        #pragma unroll
        for (int im = 0; im < 2; im++) {
            int rb = wm * 32 + im * 16 + g;
            int kb = kk * 8 + r;
            a[im][0] = __float_as_uint(sD[rb * SA + kb]);
            a[im][1] = __float_as_uint(sD[(rb + 8) * SA + kb]);
            a[im][2] = __float_as_uint(sD[rb * SA + kb + 4]);
            a[im][3] = __float_as_uint(sD[(rb + 8) * SA + kb + 4]);
        }
        #pragma unroll
        for (int jn = 0; jn < 8; jn++) {
            int nb = wn * 64 + jn * 8 + g;
            uint32_t b0 = __float_as_uint(sW1[(kk * 8 + r) * SB + nb]);
            uint32_t bv = __float_as_uint(sW1[(kk * 8 + 4 + r) * SB + nb]);
            mma8(c1[0][jn], a[0], b0, bv);
            mma8(c1[1][jn], a[1], b0, bv);
        }
    }

    #pragma unroll
    for (int im = 0; im < 2; im++) {
        int rb = wm * 32 + im * 16 + g;
        #pragma unroll
        for (int jn = 0; jn < 8; jn++) {
            int col = wn * 64 + jn * 8 + 2 * r;
            float bb0 = sB1[col], bb1 = sB1[col + 1];
            float2 lo, hi;
            lo.x = __uint_as_float(f2tf32(ssp_f(c1[im][jn][0] + bb0)));
            lo.y = __uint_as_float(f2tf32(ssp_f(c1[im][jn][1] + bb1)));
            hi.x = __uint_as_float(f2tf32(ssp_f(c1[im][jn][2] + bb0)));
            hi.y = __uint_as_float(f2tf32(ssp_f(c1[im][jn][3] + bb1)));
            *(float2*)(sT + rb * SB + col) = lo;
            *(float2*)(sT + (rb + 8) * SB + col) = hi;
        }
    }
    __syncthreads();

    // GEMM2: [128,128] @ [128,128]
    float c2[2][8][4];
    #pragma unroll
    for (int im = 0; im < 2; im++)
        #pragma unroll
        for (int jn = 0; jn < 8; jn++)
            #pragma unroll
            for (int q = 0; q < 4; q++) c2[im][jn][q] = 0.0f;

    #pragma unroll 4
    for (int kk = 0; kk < FC / 8; kk++) {
        uint32_t a[2][4];
        #pragma unroll
        for (int im = 0; im < 2; im++) {
            int rb = wm * 32 + im * 16 + g;
            int kb = kk * 8 + r;
            a[im][0] = __float_as_uint(sT[rb * SB + kb]);
            a[im][1] = __float_as_uint(sT[(rb + 8) * SB + kb]);
            a[im][2] = __float_as_uint(sT[rb * SB + kb + 4]);
            a[im][3] = __float_as_uint(sT[(rb + 8) * SB + kb + 4]);
        }
        #pragma unroll
        for (int jn = 0; jn < 8; jn++) {
            int nb = wn * 64 + jn * 8 + g;
            uint32_t b0 = __float_as_uint(sW2[(kk * 8 + r) * SB + nb]);
            uint32_t bv = __float_as_uint(sW2[(kk * 8 + 4 + r) * SB + nb]);
            mma8(c2[0][jn], a[0], b0, bv);
            mma8(c2[1][jn], a[1], b0, bv);
        }
    }

    float* lutL = g_lut + (size_t)l * NLUT * HC;
    #pragma unroll
    for (int q = 0; q < 4; q++) {
        int im = q >> 1, hi = q & 1;
        int row = wm * 32 + im * 16 + hi * 8 + g;
        int idx = t * 128 + row;
        float d = (float)idx * LUT_STEP;
        float Ce = 0.5f * (cosf(d * 0.31415926535897931f) + 1.0f);
        float* lp = lutL + (size_t)idx * HC;
        #pragma unroll
        for (int jn = 0; jn < 8; jn++) {
            int col = wn * 64 + jn * 8 + 2 * r;
            float2 o;
            o.x = (c2[im][jn][hi * 2 + 0] + sB2[col]) * Ce;
            o.y = (c2[im][jn][hi * 2 + 1] + sB2[col + 1]) * Ce;
            *(float2*)(lp + col) = o;
        }
    }
}

// ---------------- agg gather: warp per node ---------------------------------
__global__ void __launch_bounds__(256)
agg_gather_kernel(const float* __restrict__ lut)
{
    int node = blockIdx.x * 8 + (threadIdx.x >> 5);
    if (node >= NN) return;
    int lane = threadIdx.x & 31;
    int s = g_rowstart[node], e = g_rowstart[node + 1];
    float4 acc = make_float4(0.0f, 0.0f, 0.0f, 0.0f);
    #pragma unroll 2
    for (int k = s; k < e; k++) {
        int rj = g_esrc[k];
        float u = g_eu[k];
        int i0 = (int)u;
        i0 = (i0 > NLUT - 2) ? (NLUT - 2) : i0;
        float f = u - (float)i0;
        const float4* lp = (const float4*)(lut + (size_t)i0 * HC) + lane;
        float4 a = lp[0];
        float4 b = lp[32];
        float4 x = ((const float4*)(g_x + (size_t)rj * HC))[lane];
        acc.x = fmaf(fmaf(f, b.x - a.x, a.x), x.x, acc.x);
        acc.y = fmaf(fmaf(f, b.y - a.y, a.y), x.y, acc.y);
        acc.z = fmaf(fmaf(f, b.z - a.z, a.z), x.z, acc.z);
        acc.w = fmaf(fmaf(f, b.w - a.w, a.w), x.w, acc.w);
    }
    ((float4*)(g_agg + (size_t)node * HC))[lane] = acc;
}

// ---------------- fused per-layer node kernel -------------------------------
// full=1: g_v += ssp(agg@W1+b1)@W2+b2 ; then (if linW) g_x = g_v@linW
// full=0: g_x = g_v @ linW only
#define FUS_SW 0
#define FUS_SA (FUS_SW + 128 * SB)
#define FUS_SH (FUS_SA + 128 * SB)
#define FUS_B1 (FUS_SH + 128 * SB)
#define FUS_B2 (FUS_B1 + FC)
#define FUSED_SMEM_F (FUS_B2 + FC)

__global__ void __launch_bounds__(512, 1)
layer_fused_kernel(const float* __restrict__ W1, const float* __restrict__ b1,
                   const float* __restrict__ W2, const float* __restrict__ b2,
                   const float* __restrict__ linW, int full)
{
    extern __shared__ float s[];
    float* sW = s + FUS_SW;
    float* sA = s + FUS_SA;
    float* sH = s + FUS_SH;
    float* sB1 = s + FUS_B1;
    float* sB2 = s + FUS_B2;

    int tid = threadIdx.x;
    int wid = tid >> 5, lane = tid & 31;
    int g = lane >> 2, r = lane & 3;
    int wm = wid & 3, wn = wid >> 2;   // 4x4 warp grid, 32x32 tiles
    int n0 = blockIdx.x * NT;

    float c[2][4][4];

    if (full) {
        for (int i = tid; i < NT * HC; i += 512) {
            int n = n0 + (i >> 7);
            sA[(i >> 7) * SB + (i & 127)] =
                (n < NN) ? __uint_as_float(f2tf32(g_agg[(size_t)n * HC + (i & 127)])) : 0.0f;
        }
        for (int i = tid; i < HC * FC; i += 512)
            sW[(i >> 7) * SB + (i & 127)] = __uint_as_float(f2tf32(W1[i]));
        if (tid < FC) sB1[tid] = b1[tid];
        else if (tid >= 128 && tid < 128 + FC) sB2[tid - 128] = b2[tid - 128];
        __syncthreads();

        // GEMM A: h = ssp(agg @ W1 + b1)
        #pragma unroll
        for (int im = 0; im < 2; im++)
            #pragma unroll
            for (int jn = 0; jn < 4; jn++)
                #pragma unroll
                for (int q = 0; q < 4; q++) c[im][jn][q] = 0.0f;
        #pragma unroll 4
        for (int kk = 0; kk < FC / 8; kk++) {
            uint32_t a[2][4];
            #pragma unroll
            for (int im = 0; im < 2; im++) {
                int rb = wm * 32 + im * 16 + g;
                int kb = kk * 8 + r;
                a[im][0] = __float_as_uint(sA[rb * SB + kb]);
                a[im][1] = __float_as_uint(sA[(rb + 8) * SB + kb]);
                a[im][2] = __float_as_uint(sA[rb * SB + kb + 4]);
                a[im][3] = __float_as_uint(sA[(rb + 8) * SB + kb + 4]);
            }
            #pragma unroll
            for (int jn = 0; jn < 4; jn++) {
                int nb = wn * 32 + jn * 8 + g;
                uint32_t b0 = __float_as_uint(sW[(kk * 8 + r) * SB + nb]);
                uint32_t bv = __float_as_uint(sW[(kk * 8 + 4 + r) * SB + nb]);
                mma8(c[0][jn], a[0], b0, bv);
                mma8(c[1][jn], a[1], b0, bv);
            }
        }
        #pragma unroll
        for (int q = 0; q < 4; q++) {
            int im = q >> 1, hi = q & 1;
            int row = wm * 32 + im * 16 + hi * 8 + g;
            #pragma unroll
            for (int jn = 0; jn < 4; jn++) {
                int col = wn * 32 + jn * 8 + 2 * r;
                float2 o;
                o.x = __uint_as_float(f2tf32(ssp_f(c[im][jn][hi * 2 + 0] + sB1[col])));
                o.y = __uint_as_float(f2tf32(ssp_f(c[im][jn][hi * 2 + 1] + sB1[col + 1])));
                *(float2*)(sH + row * SB + col) = o;
            }
        }
        __syncthreads();
        for (int i = tid; i < HC * FC; i += 512)
            sW[(i >> 7) * SB + (i & 127)] = __uint_as_float(f2tf32(W2[i]));
        __syncthreads();

        // GEMM B: v += h @ W2 + b2 ; sA = tf32(v_new)
        #pragma unroll
        for (int im = 0; im < 2; im++)
            #pragma unroll
            for (int jn = 0; jn < 4; jn++)
                #pragma unroll
                for (int q = 0; q < 4; q++) c[im][jn][q] = 0.0f;
        #pragma unroll 4
        for (int kk = 0; kk < FC / 8; kk++) {
            uint32_t a[2][4];
            #pragma unroll
            for (int im = 0; im < 2; im++) {
                int rb = wm * 32 + im * 16 + g;
                int kb = kk * 8 + r;
                a[im][0] = __float_as_uint(sH[rb * SB + kb]);
                a[im][1] = __float_as_uint(sH[(rb + 8) * SB + kb]);
                a[im][2] = __float_as_uint(sH[rb * SB + kb + 4]);
                a[im][3] = __float_as_uint(sH[(rb + 8) * SB + kb + 4]);
            }
            #pragma unroll
            for (int jn = 0; jn < 4; jn++) {
                int nb = wn * 32 + jn * 8 + g;
                uint32_t b0 = __float_as_uint(sW[(kk * 8 + r) * SB + nb]);
                uint32_t bv = __float_as_uint(sW[(kk * 8 + 4 + r) * SB + nb]);
                mma8(c[0][jn], a[0], b0, bv);
                mma8(c[1][jn], a[1], b0, bv);
            }
        }
        #pragma unroll
        for (int q = 0; q < 4; q++) {
            int im = q >> 1, hi = q & 1;
            int row = wm * 32 + im * 16 + hi * 8 + g;
            int n = n0 + row;
            if (n >= NN) continue;
            float* vp = g_v + (size_t)n * HC;
            #pragma unroll
            for (int jn = 0; jn < 4; jn++) {
                int col = wn * 32 + jn * 8 + 2 * r;
                float2 old = *(const float2*)(vp + col);
                float2 o;
                o.x = old.x + c[im][jn][hi * 2 + 0] + sB2[col];
                o.y = old.y + c[im][jn][hi * 2 + 1] + sB2[col + 1];
                *(float2*)(vp + col) = o;
                float2 t;
                t.x = __uint_as_float(f2tf32(o.x));
                t.y = __uint_as_float(f2tf32(o.y));
                *(float2*)(sA + row * SB + col) = t;
            }
        }
        if (!linW) return;
        __syncthreads();
    } else {
        // stage sA = tf32(v)
        for (int i = tid; i < NT * HC; i += 512) {
            int n = n0 + (i >> 7);
            sA[(i >> 7) * SB + (i & 127)] =
                (n < NN) ? __uint_as_float(f2tf32(g_v[(size_t)n * HC + (i & 127)])) : 0.0f;
        }
    }

    // GEMM C: x = v_new @ linW
    for (int i = tid; i < HC * FC; i += 512)
        sW[(i >> 7) * SB + (i & 127)] = __uint_as_float(f2tf32(linW[i]));
    __syncthreads();

    #pragma unroll
    for (int im = 0; im < 2; im++)
        #pragma unroll
        for (int jn = 0; jn < 4; jn++)
            #pragma unroll
            for (int q = 0; q < 4; q++) c[im][jn][q] = 0.0f;
    #pragma unroll 4
    for (int kk = 0; kk < FC / 8; kk++) {
        uint32_t a[2][4];
        #pragma unroll
        for (int im = 0; im < 2; im++) {
            int rb = wm * 32 + im * 16 + g;
            int kb = kk * 8 + r;
            a[im][0] = __float_as_uint(sA[rb * SB + kb]);
            a[im][1] = __float_as_uint(sA[(rb + 8) * SB + kb]);
            a[im][2] = __float_as_uint(sA[rb * SB + kb + 4]);
            a[im][3] = __float_as_uint(sA[(rb + 8) * SB + kb + 4]);
        }
        #pragma unroll
        for (int jn = 0; jn < 4; jn++) {
            int nb = wn * 32 + jn * 8 + g;
            uint32_t b0 = __float_as_uint(sW[(kk * 8 + r) * SB + nb]);
            uint32_t bv = __float_as_uint(sW[(kk * 8 + 4 + r) * SB + nb]);
            mma8(c[0][jn], a[0], b0, bv);
            mma8(c[1][jn], a[1], b0, bv);
        }
    }
    #pragma unroll
    for (int q = 0; q < 4; q++) {
        int im = q >> 1, hi = q & 1;
        int row = wm * 32 + im * 16 + hi * 8 + g;
        int n = n0 + row;
        if (n >= NN) continue;
        float* xp = g_x + (size_t)n * HC;
        #pragma unroll
        for (int jn = 0; jn < 4; jn++) {
            int col = wn * 32 + jn * 8 + 2 * r;
            float2 o;
            o.x = c[im][jn][hi * 2 + 0];
            o.y = c[im][jn][hi * 2 + 1];
            *(float2*)(xp + col) = o;
        }
    }
}

// ---------------- readout ---------------------------------------------------
__global__ void readout_kernel(const int* __restrict__ batch,
                               const float* __restrict__ uW1, const float* __restrict__ ub1,
                               const float* __restrict__ uW2, const float* __restrict__ ub2,
                               float* __restrict__ out)
{
    __shared__ float sv[8][HC];
    int tid = threadIdx.x;
    int w = tid >> 5, l = tid & 31;
    int n0 = blockIdx.x * 8;
    for (int i = tid; i < 8 * HC; i += 256) {
        int n = n0 + (i >> 7);
        sv[i >> 7][i & 127] = (n < NN) ? g_v[(size_t)n * HC + (i & 127)] : 0.0f;
    }
    __syncthreads();
    int n = n0 + w;
    if (n >= NN) return;
    float a0 = 0.0f, a1 = 0.0f;
    #pragma unroll 8
    for (int h = 0; h < HC; h++) {
        float vv = sv[w][h];
        a0 += vv * uW1[h * 64 + l];
        a1 += vv * uW1[h * 64 + l + 32];
    }
    float h0 = ssp_f(a0 + ub1[l]);
    float h1 = ssp_f(a1 + ub1[l + 32]);
    float p = h0 * uW2[l] + h1 * uW2[l + 32];
    #pragma unroll
    for (int o = 16; o; o >>= 1) p += __shfl_down_sync(0xffffffffu, p, o);
    if (l == 0) atomicAdd(&out[batch[n]], p + ub2[0]);
}

// ---------------- launch ----------------------------------------------------
extern "C" void kernel_launch(void* const* d_in, const int* in_sizes, int n_in,
                              void* d_out, int out_size)
{
    const int*   z     = (const int*)d_in[0];
    const float* pos   = (const float*)d_in[1];
    const int*   batch = (const int*)d_in[2];
    const int*   eidx  = (const int*)d_in[3];
    const float* emb   = (const float*)d_in[4];
    const float* lin_W = (const float*)d_in[5];
    const float* mW1   = (const float*)d_in[6];
    const float* mb1   = (const float*)d_in[7];
    const float* mW2   = (const float*)d_in[8];
    const float* mb2   = (const float*)d_in[9];
    const float* vW1   = (const float*)d_in[10];
    const float* vb1   = (const float*)d_in[11];
    const float* vW2   = (const float*)d_in[12];
    const float* vb2   = (const float*)d_in[13];
    const float* uW1   = (const float*)d_in[14];
    const float* ub1   = (const float*)d_in[15];
    const float* uW2   = (const float*)d_in[16];
    const float* ub2   = (const float*)d_in[17];
    float* out = (float*)d_out;

    const int LUT_SMEM = LUT_SMEM_F * (int)sizeof(float);
    const int FUSED_SMEM = FUSED_SMEM_F * (int)sizeof(float);
    cudaFuncSetAttribute(lut_gen_kernel, cudaFuncAttributeMaxDynamicSharedMemorySize, LUT_SMEM);
    cudaFuncSetAttribute(layer_fused_kernel, cudaFuncAttributeMaxDynamicSharedMemorySize, FUSED_SMEM);

    init_v_kernel<<<(NN * HC + 255) / 256, 256>>>(z, emb);
    zero_cnt_kernel<<<(NN + 255) / 256, 256>>>();
    edge_pre_kernel<<<(NE + 255) / 256, 256>>>(pos, eidx);
    scan_kernel<<<1, SCAN_T>>>();
    scatter_kernel<<<(NE + 255) / 256, 256>>>(eidx);
    prep_w_kernel<<<(NLAY * FC * FC + 255) / 256, 256>>>(mW1, mW2);
    lut_gen_kernel<<<dim3(NLUT / 128, NLAY), 256, LUT_SMEM>>>(mb1, mb2);

    const int NODE_GRID = (NN + NT - 1) / NT;   // 391
    float* lutDev;
    cudaGetSymbolAddress((void**)&lutDev, g_lut);

    // x for layer 0
    layer_fused_kernel<<<NODE_GRID, 512, FUSED_SMEM>>>(nullptr, nullptr, nullptr, nullptr, lin_W, 0);
    for (int l = 0; l < NLAY; l++) {
        agg_gather_kernel<<<(NN + 7) / 8, 256>>>(lutDev + (size_t)l * NLUT * HC);
        const float* nextLin = (l + 1 < NLAY) ? (lin_W + (size_t)(l + 1) * HC * FC) : nullptr;
        layer_fused_kernel<<<NODE_GRID, 512, FUSED_SMEM>>>(
            vW1 + (size_t)l * FC * HC, vb1 + (size_t)l * HC,
            vW2 + (size_t)l * HC * HC, vb2 + (size_t)l * HC,
            nextLin, 1);
    }

    zero_out_kernel<<<1, 64>>>(out);
    readout_kernel<<<(NN + 7) / 8, 256>>>(batch, uW1, ub1, uW2, ub2, out);
    (void)in_sizes; (void)n_in; (void)out_size;
}

// round 7
// speedup vs baseline: 10.6120x; 1.0693x over previous
#include <cuda_runtime.h>
#include <cuda_fp16.h>
#include <math.h>
#include <stdint.h>

#define NN 50000
#define NE 625000
#define NGR 64
#define HC 128
#define FC 128
#define NGAUSS 50
#define KG 56                         // gaussian K padded to 56 (mult of 8)
#define NLAY 6
#define NT 128                        // node tile rows

#define NLUT 8192
#define DMAX 20.0f
#define LUT_STEP (DMAX / (float)NLUT)
#define INV_STEP ((float)NLUT / DMAX)

// smem strides (floats) — conflict-free fragment loads
#define SA 60     // sD stride (lut_gen)
#define SB 132    // weight / activation stride

// ---------------- scratch (device globals; no allocation allowed) ----------
__device__ float g_v[NN * HC];
__device__ float g_x[NN * HC];
__device__ float g_agg[NN * HC];
__device__ float g_W1t[NLAY * KG * FC];           // [l][k][n] tf32, zero-padded
__device__ float g_W2t[NLAY * FC * FC];           // [l][k][n] tf32
__device__ unsigned int g_lut_h[(size_t)NLAY * NLUT * 64]; // fp16x2 LUT rows (128 half/row)
// CSR edge structure (by destination node)
__device__ float g_uraw[NE];         // dist * INV_STEP, original edge order
__device__ int   g_cnt[NN];
__device__ int   g_fill[NN];
__device__ int   g_rowstart[NN + 1];
__device__ int   g_esrc[NE];         // source node, CSR order
__device__ float g_eu[NE];           // u, CSR order
// scan temporaries
#define SCB 256
#define SNB 196                       // 196*256 = 50176 >= NN
__device__ int g_bsum[SNB];
__device__ int g_boff[SNB];

// ---------------- helpers ---------------------------------------------------
__device__ __forceinline__ uint32_t f2tf32(float x) {
    uint32_t r;
    asm("cvt.rna.tf32.f32 %0, %1;" : "=r"(r) : "f"(x));
    return r;
}
__device__ __forceinline__ void mma8(float* c, const uint32_t* a, uint32_t b0, uint32_t b1) {
    asm volatile("mma.sync.aligned.m16n8k8.row.col.f32.tf32.tf32.f32 "
                 "{%0,%1,%2,%3},{%4,%5,%6,%7},{%8,%9},{%0,%1,%2,%3};"
                 : "+f"(c[0]), "+f"(c[1]), "+f"(c[2]), "+f"(c[3])
                 : "r"(a[0]), "r"(a[1]), "r"(a[2]), "r"(a[3]), "r"(b0), "r"(b1));
}
__device__ __forceinline__ float ssp_f(float x) {
    return fmaxf(x, 0.0f) + log1pf(expf(-fabsf(x))) - 0.69314718055994531f;
}

// ---------------- init: v = emb_table[z] -----------------------------------
__global__ void init_v_kernel(const int* __restrict__ z, const float* __restrict__ emb) {
    int idx = blockIdx.x * blockDim.x + threadIdx.x;
    if (idx < NN * HC) g_v[idx] = emb[z[idx >> 7] * HC + (idx & 127)];
}

// ---------------- CSR build -------------------------------------------------
__global__ void zero_cnt_kernel() {
    int i = blockIdx.x * blockDim.x + threadIdx.x;
    if (i < NN) { g_cnt[i] = 0; g_fill[i] = 0; }
}

__global__ void edge_pre_kernel(const float* __restrict__ pos, const int* __restrict__ eidx) {
    int e = blockIdx.x * blockDim.x + threadIdx.x;
    if (e >= NE) return;
    int r = eidx[e], c = eidx[NE + e];
    float dx = pos[3 * r] - pos[3 * c];
    float dy = pos[3 * r + 1] - pos[3 * c + 1];
    float dz = pos[3 * r + 2] - pos[3 * c + 2];
    g_uraw[e] = sqrtf(dx * dx + dy * dy + dz * dz) * INV_STEP;
    atomicAdd(&g_cnt[c], 1);
}

// 3-phase multi-block exclusive scan of g_cnt -> g_rowstart
__global__ void scan_part_kernel() {
    __shared__ int sh[SCB];
    int i = blockIdx.x * SCB + threadIdx.x;
    int v = (i < NN) ? g_cnt[i] : 0;
    sh[threadIdx.x] = v;
    __syncthreads();
    for (int off = SCB / 2; off; off >>= 1) {
        if (threadIdx.x < off) sh[threadIdx.x] += sh[threadIdx.x + off];
        __syncthreads();
    }
    if (threadIdx.x == 0) g_bsum[blockIdx.x] = sh[0];
}
__global__ void scan_top_kernel() {
    __shared__ int sh[256];
    int t = threadIdx.x;
    int v = (t < SNB) ? g_bsum[t] : 0;
    sh[t] = v;
    __syncthreads();
    for (int off = 1; off < 256; off <<= 1) {
        int u = (t >= off) ? sh[t - off] : 0;
        __syncthreads();
        sh[t] += u;
        __syncthreads();
    }
    if (t < SNB) g_boff[t] = sh[t] - v;   // exclusive
}
__global__ void scan_emit_kernel() {
    __shared__ int sh[SCB];
    int i = blockIdx.x * SCB + threadIdx.x;
    int v = (i < NN) ? g_cnt[i] : 0;
    sh[threadIdx.x] = v;
    __syncthreads();
    for (int off = 1; off < SCB; off <<= 1) {
        int u = (threadIdx.x >= off) ? sh[threadIdx.x - off] : 0;
        __syncthreads();
        sh[threadIdx.x] += u;
        __syncthreads();
    }
    if (i < NN) g_rowstart[i] = g_boff[blockIdx.x] + sh[threadIdx.x] - v;
    if (i == 0) g_rowstart[NN] = NE;
}

__global__ void scatter_kernel(const int* __restrict__ eidx) {
    int e = blockIdx.x * blockDim.x + threadIdx.x;
    if (e >= NE) return;
    int ci = eidx[NE + e];
    int pos = g_rowstart[ci] + atomicAdd(&g_fill[ci], 1);
    g_esrc[pos] = eidx[e];
    g_eu[pos] = g_uraw[e];
}

// ---------------- prep: tf32-round edge weights into padded [k][n] ----------
__global__ void prep_w_kernel(const float* __restrict__ mW1, const float* __restrict__ mW2) {
    int idx = blockIdx.x * blockDim.x + threadIdx.x;
    if (idx < NLAY * KG * FC) {
        int l = idx / (KG * FC), rem = idx % (KG * FC);
        int k = rem / FC, n = rem % FC;
        float v = (k < NGAUSS) ? mW1[(l * NGAUSS + k) * FC + n] : 0.0f;
        g_W1t[idx] = __uint_as_float(f2tf32(v));
    }
    if (idx < NLAY * FC * FC) {
        g_W2t[idx] = __uint_as_float(f2tf32(mW2[idx]));
    }
}

__global__ void zero_out_kernel(float* __restrict__ out) {
    if (threadIdx.x < NGR) out[threadIdx.x] = 0.0f;
}

// ---------------- LUT generation (tf32 mma, one tile = 128 dist samples) ----
#define OFF_SW1 0
#define OFF_SW2 (OFF_SW1 + KG * SB)
#define OFF_SD  (OFF_SW2 + FC * SB)
#define OFF_STT (OFF_SD + 128 * SA)
#define OFF_SB1 (OFF_STT + 128 * SB)
#define OFF_SB2 (OFF_SB1 + FC)
#define LUT_SMEM_F (OFF_SB2 + FC)

__global__ void __launch_bounds__(256, 1)
lut_gen_kernel(const float* __restrict__ mb1, const float* __restrict__ mb2)
{
    extern __shared__ float s[];
    float* sW1 = s + OFF_SW1;
    float* sW2 = s + OFF_SW2;
    float* sD  = s + OFF_SD;
    float* sT  = s + OFF_STT;
    float* sB1 = s + OFF_SB1;
    float* sB2 = s + OFF_SB2;

    int tid = threadIdx.x;
    int wid = tid >> 5, lane = tid & 31;
    int g = lane >> 2, r = lane & 3;
    int wm = wid & 3, wn = wid >> 2;
    int t = blockIdx.x;
    int l = blockIdx.y;

    {
        const float* w1 = g_W1t + (size_t)l * KG * FC;
        const float* w2 = g_W2t + (size_t)l * FC * FC;
        const float* b1 = mb1 + (size_t)l * FC;
        const float* b2 = mb2 + (size_t)l * FC;
        for (int i = tid; i < KG * FC; i += 256) sW1[(i >> 7) * SB + (i & 127)] = w1[i];
        for (int i = tid; i < FC * FC; i += 256) sW2[(i >> 7) * SB + (i & 127)] = w2[i];
        for (int i = tid; i < FC; i += 256) { sB1[i] = b1[i]; sB2[i] = b2[i]; }
    }
    {
        const float delta = 10.0f / 49.0f;
        const float coeff = -0.5f / (delta * delta);
        for (int i = tid; i < 128 * KG; i += 256) {
            int row = i / KG, k = i - row * KG;
            float d = (float)(t * 128 + row) * LUT_STEP;
            float dd = d - (float)k * delta;
            float v = (k < NGAUSS) ? expf(coeff * dd * dd) : 0.0f;
            sD[row * SA + k] = __uint_as_float(f2tf32(v));
        }
    }
    __syncthreads();

    // GEMM1: [128,56] @ [56,128]
    float c1[2][8][4];
    #pragma unroll
    for (int im = 0; im < 2; im++)
        #pragma unroll
        for (int jn = 0; jn < 8; jn++)
            #pragma unroll
            for (int q = 0; q < 4; q++) c1[im][jn][q] = 0.0f;

    #pragma unroll
    for (int kk = 0; kk < KG / 8; kk++) {
        uint32_t a[2][4];
        #pragma unroll
        for (int im = 0; im < 2; im++) {
            int rb = wm * 32 + im * 16 + g;
            int kb = kk * 8 + r;
            a[im][0] = __float_as_uint(sD[rb * SA + kb]);
            a[im][1] = __float_as_uint(sD[(rb + 8) * SA + kb]);
            a[im][2] = __float_as_uint(sD[rb * SA + kb + 4]);
            a[im][3] = __float_as_uint(sD[(rb + 8) * SA + kb + 4]);
        }
        #pragma unroll
        for (int jn = 0; jn < 8; jn++) {
            int nb = wn * 64 + jn * 8 + g;
            uint32_t b0 = __float_as_uint(sW1[(kk * 8 + r) * SB + nb]);
            uint32_t bv = __float_as_uint(sW1[(kk * 8 + 4 + r) * SB + nb]);
            mma8(c1[0][jn], a[0], b0, bv);
            mma8(c1[1][jn], a[1], b0, bv);
        }
    }

    #pragma unroll
    for (int im = 0; im < 2; im++) {
        int rb = wm * 32 + im * 16 + g;
        #pragma unroll
        for (int jn = 0; jn < 8; jn++) {
            int col = wn * 64 + jn * 8 + 2 * r;
            float bb0 = sB1[col], bb1 = sB1[col + 1];
            float2 lo, hi;
            lo.x = __uint_as_float(f2tf32(ssp_f(c1[im][jn][0] + bb0)));
            lo.y = __uint_as_float(f2tf32(ssp_f(c1[im][jn][1] + bb1)));
            hi.x = __uint_as_float(f2tf32(ssp_f(c1[im][jn][2] + bb0)));
            hi.y = __uint_as_float(f2tf32(ssp_f(c1[im][jn][3] + bb1)));
            *(float2*)(sT + rb * SB + col) = lo;
            *(float2*)(sT + (rb + 8) * SB + col) = hi;
        }
    }
    __syncthreads();

    // GEMM2: [128,128] @ [128,128]
    float c2[2][8][4];
    #pragma unroll
    for (int im = 0; im < 2; im++)
        #pragma unroll
        for (int jn = 0; jn < 8; jn++)
            #pragma unroll
            for (int q = 0; q < 4; q++) c2[im][jn][q] = 0.0f;

    #pragma unroll 4
    for (int kk = 0; kk < FC / 8; kk++) {
        uint32_t a[2][4];
        #pragma unroll
        for (int im = 0; im < 2; im++) {
            int rb = wm * 32 + im * 16 + g;
            int kb = kk * 8 + r;
            a[im][0] = __float_as_uint(sT[rb * SB + kb]);
            a[im][1] = __float_as_uint(sT[(rb + 8) * SB + kb]);
            a[im][2] = __float_as_uint(sT[rb * SB + kb + 4]);
            a[im][3] = __float_as_uint(sT[(rb + 8) * SB + kb + 4]);
        }
        #pragma unroll
        for (int jn = 0; jn < 8; jn++) {
            int nb = wn * 64 + jn * 8 + g;
            uint32_t b0 = __float_as_uint(sW2[(kk * 8 + r) * SB + nb]);
            uint32_t bv = __float_as_uint(sW2[(kk * 8 + 4 + r) * SB + nb]);
            mma8(c2[0][jn], a[0], b0, bv);
            mma8(c2[1][jn], a[1], b0, bv);
        }
    }

    // epilogue: + b2, * C(d), write fp16 LUT row
    unsigned int* lutL = g_lut_h + (size_t)l * NLUT * 64;
    #pragma unroll
    for (int q = 0; q < 4; q++) {
        int im = q >> 1, hi = q & 1;
        int row = wm * 32 + im * 16 + hi * 8 + g;
        int idx = t * 128 + row;
        float d = (float)idx * LUT_STEP;
        float Ce = 0.5f * (cosf(d * 0.31415926535897931f) + 1.0f);
        unsigned int* lp = lutL + (size_t)idx * 64;
        #pragma unroll
        for (int jn = 0; jn < 8; jn++) {
            int col = wn * 64 + jn * 8 + 2 * r;
            float ox = (c2[im][jn][hi * 2 + 0] + sB2[col]) * Ce;
            float oy = (c2[im][jn][hi * 2 + 1] + sB2[col + 1]) * Ce;
            __half2 h = __floats2half2_rn(ox, oy);
            lp[col >> 1] = *(unsigned int*)&h;
        }
    }
}

// ---------------- agg gather: warp per node, fp16 LUT -----------------------
__global__ void __launch_bounds__(256)
agg_gather_kernel(const unsigned int* __restrict__ lut)
{
    int node = blockIdx.x * 8 + (threadIdx.x >> 5);
    if (node >= NN) return;
    int lane = threadIdx.x & 31;
    int s = g_rowstart[node], e = g_rowstart[node + 1];
    float4 acc = make_float4(0.0f, 0.0f, 0.0f, 0.0f);
    #pragma unroll 4
    for (int k = s; k < e; k++) {
        int rj = g_esrc[k];
        float u = g_eu[k];
        int i0 = (int)u;
        i0 = (i0 > NLUT - 2) ? (NLUT - 2) : i0;
        float f = u - (float)i0;
        const uint2* la = (const uint2*)(lut + (size_t)i0 * 64) + lane;
        uint2 A = la[0];
        uint2 B = la[32];               // next LUT row (64 uints = 32 uint2)
        float4 x = ((const float4*)(g_x + (size_t)rj * HC))[lane];
        float2 a0 = __half22float2(*(__half2*)&A.x);
        float2 a1 = __half22float2(*(__half2*)&A.y);
        float2 b0 = __half22float2(*(__half2*)&B.x);
        float2 b1 = __half22float2(*(__half2*)&B.y);
        acc.x = fmaf(fmaf(f, b0.x - a0.x, a0.x), x.x, acc.x);
        acc.y = fmaf(fmaf(f, b0.y - a0.y, a0.y), x.y, acc.y);
        acc.z = fmaf(fmaf(f, b1.x - a1.x, a1.x), x.z, acc.z);
        acc.w = fmaf(fmaf(f, b1.y - a1.y, a1.y), x.w, acc.w);
    }
    ((float4*)(g_agg + (size_t)node * HC))[lane] = acc;
}

// ---------------- fused per-layer node kernel -------------------------------
// full=1: g_v += ssp(agg@W1+b1)@W2+b2 ; then (if linW) g_x = g_v@linW
// full=0: g_x = g_v @ linW only
#define FUS_SW 0
#define FUS_SA (FUS_SW + 128 * SB)
#define FUS_SH (FUS_SA + 128 * SB)
#define FUS_B1 (FUS_SH + 128 * SB)
#define FUS_B2 (FUS_B1 + FC)
#define FUSED_SMEM_F (FUS_B2 + FC)

__global__ void __launch_bounds__(512, 1)
layer_fused_kernel(const float* __restrict__ W1, const float* __restrict__ b1,
                   const float* __restrict__ W2, const float* __restrict__ b2,
                   const float* __restrict__ linW, int full)
{
    extern __shared__ float s[];
    float* sW = s + FUS_SW;
    float* sA = s + FUS_SA;
    float* sH = s + FUS_SH;
    float* sB1 = s + FUS_B1;
    float* sB2 = s + FUS_B2;

    int tid = threadIdx.x;
    int wid = tid >> 5, lane = tid & 31;
    int g = lane >> 2, r = lane & 3;
    int wm = wid & 3, wn = wid >> 2;   // 4x4 warp grid, 32x32 tiles
    int n0 = blockIdx.x * NT;

    float c[2][4][4];

    if (full) {
        for (int i = tid; i < NT * HC; i += 512) {
            int n = n0 + (i >> 7);
            sA[(i >> 7) * SB + (i & 127)] =
                (n < NN) ? __uint_as_float(f2tf32(g_agg[(size_t)n * HC + (i & 127)])) : 0.0f;
        }
        for (int i = tid; i < HC * FC; i += 512)
            sW[(i >> 7) * SB + (i & 127)] = __uint_as_float(f2tf32(W1[i]));
        if (tid < FC) sB1[tid] = b1[tid];
        else if (tid >= 128 && tid < 128 + FC) sB2[tid - 128] = b2[tid - 128];
        __syncthreads();

        // GEMM A: h = ssp(agg @ W1 + b1)
        #pragma unroll
        for (int im = 0; im < 2; im++)
            #pragma unroll
            for (int jn = 0; jn < 4; jn++)
                #pragma unroll
                for (int q = 0; q < 4; q++) c[im][jn][q] = 0.0f;
        #pragma unroll 4
        for (int kk = 0; kk < FC / 8; kk++) {
            uint32_t a[2][4];
            #pragma unroll
            for (int im = 0; im < 2; im++) {
                int rb = wm * 32 + im * 16 + g;
                int kb = kk * 8 + r;
                a[im][0] = __float_as_uint(sA[rb * SB + kb]);
                a[im][1] = __float_as_uint(sA[(rb + 8) * SB + kb]);
                a[im][2] = __float_as_uint(sA[rb * SB + kb + 4]);
                a[im][3] = __float_as_uint(sA[(rb + 8) * SB + kb + 4]);
            }
            #pragma unroll
            for (int jn = 0; jn < 4; jn++) {
                int nb = wn * 32 + jn * 8 + g;
                uint32_t b0 = __float_as_uint(sW[(kk * 8 + r) * SB + nb]);
                uint32_t bv = __float_as_uint(sW[(kk * 8 + 4 + r) * SB + nb]);
                mma8(c[0][jn], a[0], b0, bv);
                mma8(c[1][jn], a[1], b0, bv);
            }
        }
        #pragma unroll
        for (int q = 0; q < 4; q++) {
            int im = q >> 1, hi = q & 1;
            int row = wm * 32 + im * 16 + hi * 8 + g;
            #pragma unroll
            for (int jn = 0; jn < 4; jn++) {
                int col = wn * 32 + jn * 8 + 2 * r;
                float2 o;
                o.x = __uint_as_float(f2tf32(ssp_f(c[im][jn][hi * 2 + 0] + sB1[col])));
                o.y = __uint_as_float(f2tf32(ssp_f(c[im][jn][hi * 2 + 1] + sB1[col + 1])));
                *(float2*)(sH + row * SB + col) = o;
            }
        }
        __syncthreads();
        for (int i = tid; i < HC * FC; i += 512)
            sW[(i >> 7) * SB + (i & 127)] = __uint_as_float(f2tf32(W2[i]));
        __syncthreads();

        // GEMM B: v += h @ W2 + b2 ; sA = tf32(v_new)
        #pragma unroll
        for (int im = 0; im < 2; im++)
            #pragma unroll
            for (int jn = 0; jn < 4; jn++)
                #pragma unroll
                for (int q = 0; q < 4; q++) c[im][jn][q] = 0.0f;
        #pragma unroll 4
        for (int kk = 0; kk < FC / 8; kk++) {
            uint32_t a[2][4];
            #pragma unroll
            for (int im = 0; im < 2; im++) {
                int rb = wm * 32 + im * 16 + g;
                int kb = kk * 8 + r;
                a[im][0] = __float_as_uint(sH[rb * SB + kb]);
                a[im][1] = __float_as_uint(sH[(rb + 8) * SB + kb]);
                a[im][2] = __float_as_uint(sH[rb * SB + kb + 4]);
                a[im][3] = __float_as_uint(sH[(rb + 8) * SB + kb + 4]);
            }
            #pragma unroll
            for (int jn = 0; jn < 4; jn++) {
                int nb = wn * 32 + jn * 8 + g;
                uint32_t b0 = __float_as_uint(sW[(kk * 8 + r) * SB + nb]);
                uint32_t bv = __float_as_uint(sW[(kk * 8 + 4 + r) * SB + nb]);
                mma8(c[0][jn], a[0], b0, bv);
                mma8(c[1][jn], a[1], b0, bv);
            }
        }
        #pragma unroll
        for (int q = 0; q < 4; q++) {
            int im = q >> 1, hi = q & 1;
            int row = wm * 32 + im * 16 + hi * 8 + g;
            int n = n0 + row;
            if (n >= NN) continue;
            float* vp = g_v + (size_t)n * HC;
            #pragma unroll
            for (int jn = 0; jn < 4; jn++) {
                int col = wn * 32 + jn * 8 + 2 * r;
                float2 old = *(const float2*)(vp + col);
                float2 o;
                o.x = old.x + c[im][jn][hi * 2 + 0] + sB2[col];
                o.y = old.y + c[im][jn][hi * 2 + 1] + sB2[col + 1];
                *(float2*)(vp + col) = o;
                float2 t;
                t.x = __uint_as_float(f2tf32(o.x));
                t.y = __uint_as_float(f2tf32(o.y));
                *(float2*)(sA + row * SB + col) = t;
            }
        }
        if (!linW) return;
        __syncthreads();
    } else {
        for (int i = tid; i < NT * HC; i += 512) {
            int n = n0 + (i >> 7);
            sA[(i >> 7) * SB + (i & 127)] =
                (n < NN) ? __uint_as_float(f2tf32(g_v[(size_t)n * HC + (i & 127)])) : 0.0f;
        }
    }

    // GEMM C: x = v_new @ linW
    for (int i = tid; i < HC * FC; i += 512)
        sW[(i >> 7) * SB + (i & 127)] = __uint_as_float(f2tf32(linW[i]));
    __syncthreads();

    #pragma unroll
    for (int im = 0; im < 2; im++)
        #pragma unroll
        for (int jn = 0; jn < 4; jn++)
            #pragma unroll
            for (int q = 0; q < 4; q++) c[im][jn][q] = 0.0f;
    #pragma unroll 4
    for (int kk = 0; kk < FC / 8; kk++) {
        uint32_t a[2][4];
        #pragma unroll
        for (int im = 0; im < 2; im++) {
            int rb = wm * 32 + im * 16 + g;
            int kb = kk * 8 + r;
            a[im][0] = __float_as_uint(sA[rb * SB + kb]);
            a[im][1] = __float_as_uint(sA[(rb + 8) * SB + kb]);
            a[im][2] = __float_as_uint(sA[rb * SB + kb + 4]);
            a[im][3] = __float_as_uint(sA[(rb + 8) * SB + kb + 4]);
        }
        #pragma unroll
        for (int jn = 0; jn < 4; jn++) {
            int nb = wn * 32 + jn * 8 + g;
            uint32_t b0 = __float_as_uint(sW[(kk * 8 + r) * SB + nb]);
            uint32_t bv = __float_as_uint(sW[(kk * 8 + 4 + r) * SB + nb]);
            mma8(c[0][jn], a[0], b0, bv);
            mma8(c[1][jn], a[1], b0, bv);
        }
    }
    #pragma unroll
    for (int q = 0; q < 4; q++) {
        int im = q >> 1, hi = q & 1;
        int row = wm * 32 + im * 16 + hi * 8 + g;
        int n = n0 + row;
        if (n >= NN) continue;
        float* xp = g_x + (size_t)n * HC;
        #pragma unroll
        for (int jn = 0; jn < 4; jn++) {
            int col = wn * 32 + jn * 8 + 2 * r;
            float2 o;
            o.x = c[im][jn][hi * 2 + 0];
            o.y = c[im][jn][hi * 2 + 1];
            *(float2*)(xp + col) = o;
        }
    }
}

// ---------------- readout ---------------------------------------------------
__global__ void readout_kernel(const int* __restrict__ batch,
                               const float* __restrict__ uW1, const float* __restrict__ ub1,
                               const float* __restrict__ uW2, const float* __restrict__ ub2,
                               float* __restrict__ out)
{
    __shared__ float sv[8][HC];
    int tid = threadIdx.x;
    int w = tid >> 5, l = tid & 31;
    int n0 = blockIdx.x * 8;
    for (int i = tid; i < 8 * HC; i += 256) {
        int n = n0 + (i >> 7);
        sv[i >> 7][i & 127] = (n < NN) ? g_v[(size_t)n * HC + (i & 127)] : 0.0f;
    }
    __syncthreads();
    int n = n0 + w;
    if (n >= NN) return;
    float a0 = 0.0f, a1 = 0.0f;
    #pragma unroll 8
    for (int h = 0; h < HC; h++) {
        float vv = sv[w][h];
        a0 += vv * uW1[h * 64 + l];
        a1 += vv * uW1[h * 64 + l + 32];
    }
    float h0 = ssp_f(a0 + ub1[l]);
    float h1 = ssp_f(a1 + ub1[l + 32]);
    float p = h0 * uW2[l] + h1 * uW2[l + 32];
    #pragma unroll
    for (int o = 16; o; o >>= 1) p += __shfl_down_sync(0xffffffffu, p, o);
    if (l == 0) atomicAdd(&out[batch[n]], p + ub2[0]);
}

// ---------------- launch ----------------------------------------------------
extern "C" void kernel_launch(void* const* d_in, const int* in_sizes, int n_in,
                              void* d_out, int out_size)
{
    const int*   z     = (const int*)d_in[0];
    const float* pos   = (const float*)d_in[1];
    const int*   batch = (const int*)d_in[2];
    const int*   eidx  = (const int*)d_in[3];
    const float* emb   = (const float*)d_in[4];
    const float* lin_W = (const float*)d_in[5];
    const float* mW1   = (const float*)d_in[6];
    const float* mb1   = (const float*)d_in[7];
    const float* mW2   = (const float*)d_in[8];
    const float* mb2   = (const float*)d_in[9];
    const float* vW1   = (const float*)d_in[10];
    const float* vb1   = (const float*)d_in[11];
    const float* vW2   = (const float*)d_in[12];
    const float* vb2   = (const float*)d_in[13];
    const float* uW1   = (const float*)d_in[14];
    const float* ub1   = (const float*)d_in[15];
    const float* uW2   = (const float*)d_in[16];
    const float* ub2   = (const float*)d_in[17];
    float* out = (float*)d_out;

    const int LUT_SMEM = LUT_SMEM_F * (int)sizeof(float);
    const int FUSED_SMEM = FUSED_SMEM_F * (int)sizeof(float);
    cudaFuncSetAttribute(lut_gen_kernel, cudaFuncAttributeMaxDynamicSharedMemorySize, LUT_SMEM);
    cudaFuncSetAttribute(layer_fused_kernel, cudaFuncAttributeMaxDynamicSharedMemorySize, FUSED_SMEM);

    init_v_kernel<<<(NN * HC + 255) / 256, 256>>>(z, emb);
    zero_cnt_kernel<<<(NN + 255) / 256, 256>>>();
    edge_pre_kernel<<<(NE + 255) / 256, 256>>>(pos, eidx);
    scan_part_kernel<<<SNB, SCB>>>();
    scan_top_kernel<<<1, 256>>>();
    scan_emit_kernel<<<SNB, SCB>>>();
    scatter_kernel<<<(NE + 255) / 256, 256>>>(eidx);
    prep_w_kernel<<<(NLAY * FC * FC + 255) / 256, 256>>>(mW1, mW2);
    lut_gen_kernel<<<dim3(NLUT / 128, NLAY), 256, LUT_SMEM>>>(mb1, mb2);

    const int NODE_GRID = (NN + NT - 1) / NT;   // 391
    unsigned int* lutDev;
    cudaGetSymbolAddress((void**)&lutDev, g_lut_h);

    layer_fused_kernel<<<NODE_GRID, 512, FUSED_SMEM>>>(nullptr, nullptr, nullptr, nullptr, lin_W, 0);
    for (int l = 0; l < NLAY; l++) {
        agg_gather_kernel<<<(NN + 7) / 8, 256>>>(lutDev + (size_t)l * NLUT * 64);
        const float* nextLin = (l + 1 < NLAY) ? (lin_W + (size_t)(l + 1) * HC * FC) : nullptr;
        layer_fused_kernel<<<NODE_GRID, 512, FUSED_SMEM>>>(
            vW1 + (size_t)l * FC * HC, vb1 + (size_t)l * HC,
            vW2 + (size_t)l * HC * HC, vb2 + (size_t)l * HC,
            nextLin, 1);
    }

    zero_out_kernel<<<1, 64>>>(out);
    readout_kernel<<<(NN + 7) / 8, 256>>>(batch, uW1, ub1, uW2, ub2, out);
    (void)in_sizes; (void)n_in; (void)out_size;
}

// round 8
// speedup vs baseline: 11.3023x; 1.0650x over previous
#include <cuda_runtime.h>
#include <cuda_fp16.h>
#include <math.h>
#include <stdint.h>

#define NN 50000
#define NE 625000
#define NGR 64
#define HC 128
#define FC 128
#define NGAUSS 50
#define KG 56                         // gaussian K padded to 56 (mult of 8)
#define NLAY 6
#define NT 128                        // node tile rows

#define NLUT 4096
#define DMAX 20.0f
#define LUT_STEP (DMAX / (float)NLUT)
#define INV_STEP ((float)NLUT / DMAX)

// smem strides (floats) — conflict-free fragment loads
#define SA 60     // sD stride (lut_gen)
#define SB 132    // weight / activation stride

// ---------------- scratch (device globals; no allocation allowed) ----------
__device__ float g_v[NN * HC];
__device__ unsigned int g_xh[NN * 64];            // x = v@linW, fp16x2 packed
__device__ float g_agg[NN * HC];
__device__ float g_W1t[NLAY * KG * FC];           // [l][k][n] tf32, zero-padded
__device__ float g_W2t[NLAY * FC * FC];           // [l][k][n] tf32
__device__ unsigned int g_lut_h[(size_t)NLAY * NLUT * 64]; // fp16x2 LUT rows
// CSR edge structure (by destination node)
__device__ float g_uraw[NE];         // dist * INV_STEP, original edge order
__device__ int   g_cnt[NN];
__device__ int   g_fill[NN];
__device__ int   g_rowstart[NN + 1];
__device__ int   g_esrc[NE];         // source node, CSR order
__device__ float g_eu[NE];           // u, CSR order
// scan temporaries
#define SCB 256
#define SNB 196                       // 196*256 = 50176 >= NN
__device__ int g_bsum[SNB];
__device__ int g_boff[SNB];

// ---------------- helpers ---------------------------------------------------
__device__ __forceinline__ uint32_t f2tf32(float x) {
    uint32_t r;
    asm("cvt.rna.tf32.f32 %0, %1;" : "=r"(r) : "f"(x));
    return r;
}
__device__ __forceinline__ void mma8(float* c, const uint32_t* a, uint32_t b0, uint32_t b1) {
    asm volatile("mma.sync.aligned.m16n8k8.row.col.f32.tf32.tf32.f32 "
                 "{%0,%1,%2,%3},{%4,%5,%6,%7},{%8,%9},{%0,%1,%2,%3};"
                 : "+f"(c[0]), "+f"(c[1]), "+f"(c[2]), "+f"(c[3])
                 : "r"(a[0]), "r"(a[1]), "r"(a[2]), "r"(a[3]), "r"(b0), "r"(b1));
}
__device__ __forceinline__ float ssp_f(float x) {
    return fmaxf(x, 0.0f) + log1pf(expf(-fabsf(x))) - 0.69314718055994531f;
}

// ---------------- init: v = emb_table[z] -----------------------------------
__global__ void init_v_kernel(const int* __restrict__ z, const float* __restrict__ emb) {
    int idx = blockIdx.x * blockDim.x + threadIdx.x;
    if (idx < NN * HC) g_v[idx] = emb[z[idx >> 7] * HC + (idx & 127)];
}

// ---------------- CSR build -------------------------------------------------
__global__ void zero_cnt_kernel() {
    int i = blockIdx.x * blockDim.x + threadIdx.x;
    if (i < NN) { g_cnt[i] = 0; g_fill[i] = 0; }
}

__global__ void edge_pre_kernel(const float* __restrict__ pos, const int* __restrict__ eidx) {
    int e = blockIdx.x * blockDim.x + threadIdx.x;
    if (e >= NE) return;
    int r = eidx[e], c = eidx[NE + e];
    float dx = pos[3 * r] - pos[3 * c];
    float dy = pos[3 * r + 1] - pos[3 * c + 1];
    float dz = pos[3 * r + 2] - pos[3 * c + 2];
    g_uraw[e] = sqrtf(dx * dx + dy * dy + dz * dz) * INV_STEP;
    atomicAdd(&g_cnt[c], 1);
}

// 3-phase multi-block exclusive scan of g_cnt -> g_rowstart
__global__ void scan_part_kernel() {
    __shared__ int sh[SCB];
    int i = blockIdx.x * SCB + threadIdx.x;
    int v = (i < NN) ? g_cnt[i] : 0;
    sh[threadIdx.x] = v;
    __syncthreads();
    for (int off = SCB / 2; off; off >>= 1) {
        if (threadIdx.x < off) sh[threadIdx.x] += sh[threadIdx.x + off];
        __syncthreads();
    }
    if (threadIdx.x == 0) g_bsum[blockIdx.x] = sh[0];
}
__global__ void scan_top_kernel() {
    __shared__ int sh[256];
    int t = threadIdx.x;
    int v = (t < SNB) ? g_bsum[t] : 0;
    sh[t] = v;
    __syncthreads();
    for (int off = 1; off < 256; off <<= 1) {
        int u = (t >= off) ? sh[t - off] : 0;
        __syncthreads();
        sh[t] += u;
        __syncthreads();
    }
    if (t < SNB) g_boff[t] = sh[t] - v;   // exclusive
}
__global__ void scan_emit_kernel() {
    __shared__ int sh[SCB];
    int i = blockIdx.x * SCB + threadIdx.x;
    int v = (i < NN) ? g_cnt[i] : 0;
    sh[threadIdx.x] = v;
    __syncthreads();
    for (int off = 1; off < SCB; off <<= 1) {
        int u = (threadIdx.x >= off) ? sh[threadIdx.x - off] : 0;
        __syncthreads();
        sh[threadIdx.x] += u;
        __syncthreads();
    }
    if (i < NN) g_rowstart[i] = g_boff[blockIdx.x] + sh[threadIdx.x] - v;
    if (i == 0) g_rowstart[NN] = NE;
}

__global__ void scatter_kernel(const int* __restrict__ eidx) {
    int e = blockIdx.x * blockDim.x + threadIdx.x;
    if (e >= NE) return;
    int ci = eidx[NE + e];
    int pos = g_rowstart[ci] + atomicAdd(&g_fill[ci], 1);
    g_esrc[pos] = eidx[e];
    g_eu[pos] = g_uraw[e];
}

// ---------------- prep: tf32-round edge weights into padded [k][n] ----------
__global__ void prep_w_kernel(const float* __restrict__ mW1, const float* __restrict__ mW2) {
    int idx = blockIdx.x * blockDim.x + threadIdx.x;
    if (idx < NLAY * KG * FC) {
        int l = idx / (KG * FC), rem = idx % (KG * FC);
        int k = rem / FC, n = rem % FC;
        float v = (k < NGAUSS) ? mW1[(l * NGAUSS + k) * FC + n] : 0.0f;
        g_W1t[idx] = __uint_as_float(f2tf32(v));
    }
    if (idx < NLAY * FC * FC) {
        g_W2t[idx] = __uint_as_float(f2tf32(mW2[idx]));
    }
}

__global__ void zero_out_kernel(float* __restrict__ out) {
    if (threadIdx.x < NGR) out[threadIdx.x] = 0.0f;
}

// ---------------- LUT generation (tf32 mma, one tile = 128 dist samples) ----
#define OFF_SW1 0
#define OFF_SW2 (OFF_SW1 + KG * SB)
#define OFF_SD  (OFF_SW2 + FC * SB)
#define OFF_STT (OFF_SD + 128 * SA)
#define OFF_SB1 (OFF_STT + 128 * SB)
#define OFF_SB2 (OFF_SB1 + FC)
#define LUT_SMEM_F (OFF_SB2 + FC)

__global__ void __launch_bounds__(256, 1)
lut_gen_kernel(const float* __restrict__ mb1, const float* __restrict__ mb2)
{
    extern __shared__ float s[];
    float* sW1 = s + OFF_SW1;
    float* sW2 = s + OFF_SW2;
    float* sD  = s + OFF_SD;
    float* sT  = s + OFF_STT;
    float* sB1 = s + OFF_SB1;
    float* sB2 = s + OFF_SB2;

    int tid = threadIdx.x;
    int wid = tid >> 5, lane = tid & 31;
    int g = lane >> 2, r = lane & 3;
    int wm = wid & 3, wn = wid >> 2;
    int t = blockIdx.x;
    int l = blockIdx.y;

    {
        const float* w1 = g_W1t + (size_t)l * KG * FC;
        const float* w2 = g_W2t + (size_t)l * FC * FC;
        const float* b1 = mb1 + (size_t)l * FC;
        const float* b2 = mb2 + (size_t)l * FC;
        for (int i = tid; i < KG * FC; i += 256) sW1[(i >> 7) * SB + (i & 127)] = w1[i];
        for (int i = tid; i < FC * FC; i += 256) sW2[(i >> 7) * SB + (i & 127)] = w2[i];
        for (int i = tid; i < FC; i += 256) { sB1[i] = b1[i]; sB2[i] = b2[i]; }
    }
    {
        const float delta = 10.0f / 49.0f;
        const float coeff = -0.5f / (delta * delta);
        for (int i = tid; i < 128 * KG; i += 256) {
            int row = i / KG, k = i - row * KG;
            float d = (float)(t * 128 + row) * LUT_STEP;
            float dd = d - (float)k * delta;
            float v = (k < NGAUSS) ? expf(coeff * dd * dd) : 0.0f;
            sD[row * SA + k] = __uint_as_float(f2tf32(v));
        }
    }
    __syncthreads();

    // GEMM1: [128,56] @ [56,128]
    float c1[2][8][4];
    #pragma unroll
    for (int im = 0; im < 2; im++)
        #pragma unroll
        for (int jn = 0; jn < 8; jn++)
            #pragma unroll
            for (int q = 0; q < 4; q++) c1[im][jn][q] = 0.0f;

    #pragma unroll
    for (int kk = 0; kk < KG / 8; kk++) {
        uint32_t a[2][4];
        #pragma unroll
        for (int im = 0; im < 2; im++) {
            int rb = wm * 32 + im * 16 + g;
            int kb = kk * 8 + r;
            a[im][0] = __float_as_uint(sD[rb * SA + kb]);
            a[im][1] = __float_as_uint(sD[(rb + 8) * SA + kb]);
            a[im][2] = __float_as_uint(sD[rb * SA + kb + 4]);
            a[im][3] = __float_as_uint(sD[(rb + 8) * SA + kb + 4]);
        }
        #pragma unroll
        for (int jn = 0; jn < 8; jn++) {
            int nb = wn * 64 + jn * 8 + g;
            uint32_t b0 = __float_as_uint(sW1[(kk * 8 + r) * SB + nb]);
            uint32_t bv = __float_as_uint(sW1[(kk * 8 + 4 + r) * SB + nb]);
            mma8(c1[0][jn], a[0], b0, bv);
            mma8(c1[1][jn], a[1], b0, bv);
        }
    }

    #pragma unroll
    for (int im = 0; im < 2; im++) {
        int rb = wm * 32 + im * 16 + g;
        #pragma unroll
        for (int jn = 0; jn < 8; jn++) {
            int col = wn * 64 + jn * 8 + 2 * r;
            float bb0 = sB1[col], bb1 = sB1[col + 1];
            float2 lo, hi;
            lo.x = __uint_as_float(f2tf32(ssp_f(c1[im][jn][0] + bb0)));
            lo.y = __uint_as_float(f2tf32(ssp_f(c1[im][jn][1] + bb1)));
            hi.x = __uint_as_float(f2tf32(ssp_f(c1[im][jn][2] + bb0)));
            hi.y = __uint_as_float(f2tf32(ssp_f(c1[im][jn][3] + bb1)));
            *(float2*)(sT + rb * SB + col) = lo;
            *(float2*)(sT + (rb + 8) * SB + col) = hi;
        }
    }
    __syncthreads();

    // GEMM2: [128,128] @ [128,128]
    float c2[2][8][4];
    #pragma unroll
    for (int im = 0; im < 2; im++)
        #pragma unroll
        for (int jn = 0; jn < 8; jn++)
            #pragma unroll
            for (int q = 0; q < 4; q++) c2[im][jn][q] = 0.0f;

    #pragma unroll 4
    for (int kk = 0; kk < FC / 8; kk++) {
        uint32_t a[2][4];
        #pragma unroll
        for (int im = 0; im < 2; im++) {
            int rb = wm * 32 + im * 16 + g;
            int kb = kk * 8 + r;
            a[im][0] = __float_as_uint(sT[rb * SB + kb]);
            a[im][1] = __float_as_uint(sT[(rb + 8) * SB + kb]);
            a[im][2] = __float_as_uint(sT[rb * SB + kb + 4]);
            a[im][3] = __float_as_uint(sT[(rb + 8) * SB + kb + 4]);
        }
        #pragma unroll
        for (int jn = 0; jn < 8; jn++) {
            int nb = wn * 64 + jn * 8 + g;
            uint32_t b0 = __float_as_uint(sW2[(kk * 8 + r) * SB + nb]);
            uint32_t bv = __float_as_uint(sW2[(kk * 8 + 4 + r) * SB + nb]);
            mma8(c2[0][jn], a[0], b0, bv);
            mma8(c2[1][jn], a[1], b0, bv);
        }
    }

    // epilogue: + b2, * C(d), write fp16 LUT row
    unsigned int* lutL = g_lut_h + (size_t)l * NLUT * 64;
    #pragma unroll
    for (int q = 0; q < 4; q++) {
        int im = q >> 1, hi = q & 1;
        int row = wm * 32 + im * 16 + hi * 8 + g;
        int idx = t * 128 + row;
        float d = (float)idx * LUT_STEP;
        float Ce = 0.5f * (cosf(d * 0.31415926535897931f) + 1.0f);
        unsigned int* lp = lutL + (size_t)idx * 64;
        #pragma unroll
        for (int jn = 0; jn < 8; jn++) {
            int col = wn * 64 + jn * 8 + 2 * r;
            float ox = (c2[im][jn][hi * 2 + 0] + sB2[col]) * Ce;
            float oy = (c2[im][jn][hi * 2 + 1] + sB2[col + 1]) * Ce;
            __half2 h = __floats2half2_rn(ox, oy);
            lp[col >> 1] = *(unsigned int*)&h;
        }
    }
}

// ---------------- agg gather: warp per node, fp16 LUT + fp16 x --------------
__global__ void __launch_bounds__(256)
agg_gather_kernel(const unsigned int* __restrict__ lut)
{
    int node = blockIdx.x * 8 + (threadIdx.x >> 5);
    if (node >= NN) return;
    int lane = threadIdx.x & 31;
    int s = g_rowstart[node], e = g_rowstart[node + 1];
    float4 acc = make_float4(0.0f, 0.0f, 0.0f, 0.0f);
    #pragma unroll 4
    for (int k = s; k < e; k++) {
        int rj = g_esrc[k];
        float u = g_eu[k];
        int i0 = (int)u;
        i0 = (i0 > NLUT - 2) ? (NLUT - 2) : i0;
        float f = u - (float)i0;
        const uint2* la = (const uint2*)(lut + (size_t)i0 * 64) + lane;
        uint2 A = la[0];
        uint2 B = la[32];               // next LUT row
        uint2 X = ((const uint2*)(g_xh + (size_t)rj * 64))[lane];
        float2 a0 = __half22float2(*(__half2*)&A.x);
        float2 a1 = __half22float2(*(__half2*)&A.y);
        float2 b0 = __half22float2(*(__half2*)&B.x);
        float2 b1 = __half22float2(*(__half2*)&B.y);
        float2 x0 = __half22float2(*(__half2*)&X.x);
        float2 x1 = __half22float2(*(__half2*)&X.y);
        acc.x = fmaf(fmaf(f, b0.x - a0.x, a0.x), x0.x, acc.x);
        acc.y = fmaf(fmaf(f, b0.y - a0.y, a0.y), x0.y, acc.y);
        acc.z = fmaf(fmaf(f, b1.x - a1.x, a1.x), x1.x, acc.z);
        acc.w = fmaf(fmaf(f, b1.y - a1.y, a1.y), x1.y, acc.w);
    }
    ((float4*)(g_agg + (size_t)node * HC))[lane] = acc;
}

// ---------------- fused per-layer node kernel -------------------------------
// full=1: g_v += ssp(agg@W1+b1)@W2+b2 ; then (if linW) g_xh = fp16(v@linW)
// full=0: g_xh = fp16(g_v @ linW) only
#define FUS_SW 0
#define FUS_SA (FUS_SW + 128 * SB)
#define FUS_SH (FUS_SA + 128 * SB)
#define FUS_B1 (FUS_SH + 128 * SB)
#define FUS_B2 (FUS_B1 + FC)
#define FUSED_SMEM_F (FUS_B2 + FC)

__global__ void __launch_bounds__(512, 1)
layer_fused_kernel(const float* __restrict__ W1, const float* __restrict__ b1,
                   const float* __restrict__ W2, const float* __restrict__ b2,
                   const float* __restrict__ linW, int full)
{
    extern __shared__ float s[];
    float* sW = s + FUS_SW;
    float* sA = s + FUS_SA;
    float* sH = s + FUS_SH;
    float* sB1 = s + FUS_B1;
    float* sB2 = s + FUS_B2;

    int tid = threadIdx.x;
    int wid = tid >> 5, lane = tid & 31;
    int g = lane >> 2, r = lane & 3;
    int wm = wid & 3, wn = wid >> 2;   // 4x4 warp grid, 32x32 tiles
    int n0 = blockIdx.x * NT;

    float c[2][4][4];

    if (full) {
        for (int i = tid; i < NT * HC; i += 512) {
            int n = n0 + (i >> 7);
            sA[(i >> 7) * SB + (i & 127)] =
                (n < NN) ? __uint_as_float(f2tf32(g_agg[(size_t)n * HC + (i & 127)])) : 0.0f;
        }
        for (int i = tid; i < HC * FC; i += 512)
            sW[(i >> 7) * SB + (i & 127)] = __uint_as_float(f2tf32(W1[i]));
        if (tid < FC) sB1[tid] = b1[tid];
        else if (tid >= 128 && tid < 128 + FC) sB2[tid - 128] = b2[tid - 128];
        __syncthreads();

        // GEMM A: h = ssp(agg @ W1 + b1)
        #pragma unroll
        for (int im = 0; im < 2; im++)
            #pragma unroll
            for (int jn = 0; jn < 4; jn++)
                #pragma unroll
                for (int q = 0; q < 4; q++) c[im][jn][q] = 0.0f;
        #pragma unroll 4
        for (int kk = 0; kk < FC / 8; kk++) {
            uint32_t a[2][4];
            #pragma unroll
            for (int im = 0; im < 2; im++) {
                int rb = wm * 32 + im * 16 + g;
                int kb = kk * 8 + r;
                a[im][0] = __float_as_uint(sA[rb * SB + kb]);
                a[im][1] = __float_as_uint(sA[(rb + 8) * SB + kb]);
                a[im][2] = __float_as_uint(sA[rb * SB + kb + 4]);
                a[im][3] = __float_as_uint(sA[(rb + 8) * SB + kb + 4]);
            }
            #pragma unroll
            for (int jn = 0; jn < 4; jn++) {
                int nb = wn * 32 + jn * 8 + g;
                uint32_t b0 = __float_as_uint(sW[(kk * 8 + r) * SB + nb]);
                uint32_t bv = __float_as_uint(sW[(kk * 8 + 4 + r) * SB + nb]);
                mma8(c[0][jn], a[0], b0, bv);
                mma8(c[1][jn], a[1], b0, bv);
            }
        }
        #pragma unroll
        for (int q = 0; q < 4; q++) {
            int im = q >> 1, hi = q & 1;
            int row = wm * 32 + im * 16 + hi * 8 + g;
            #pragma unroll
            for (int jn = 0; jn < 4; jn++) {
                int col = wn * 32 + jn * 8 + 2 * r;
                float2 o;
                o.x = __uint_as_float(f2tf32(ssp_f(c[im][jn][hi * 2 + 0] + sB1[col])));
                o.y = __uint_as_float(f2tf32(ssp_f(c[im][jn][hi * 2 + 1] + sB1[col + 1])));
                *(float2*)(sH + row * SB + col) = o;
            }
        }
        __syncthreads();
        for (int i = tid; i < HC * FC; i += 512)
            sW[(i >> 7) * SB + (i & 127)] = __uint_as_float(f2tf32(W2[i]));
        __syncthreads();

        // GEMM B: v += h @ W2 + b2 ; sA = tf32(v_new)
        #pragma unroll
        for (int im = 0; im < 2; im++)
            #pragma unroll
            for (int jn = 0; jn < 4; jn++)
                #pragma unroll
                for (int q = 0; q < 4; q++) c[im][jn][q] = 0.0f;
        #pragma unroll 4
        for (int kk = 0; kk < FC / 8; kk++) {
            uint32_t a[2][4];
            #pragma unroll
            for (int im = 0; im < 2; im++) {
                int rb = wm * 32 + im * 16 + g;
                int kb = kk * 8 + r;
                a[im][0] = __float_as_uint(sH[rb * SB + kb]);
                a[im][1] = __float_as_uint(sH[(rb + 8) * SB + kb]);
                a[im][2] = __float_as_uint(sH[rb * SB + kb + 4]);
                a[im][3] = __float_as_uint(sH[(rb + 8) * SB + kb + 4]);
            }
            #pragma unroll
            for (int jn = 0; jn < 4; jn++) {
                int nb = wn * 32 + jn * 8 + g;
                uint32_t b0 = __float_as_uint(sW[(kk * 8 + r) * SB + nb]);
                uint32_t bv = __float_as_uint(sW[(kk * 8 + 4 + r) * SB + nb]);
                mma8(c[0][jn], a[0], b0, bv);
                mma8(c[1][jn], a[1], b0, bv);
            }
        }
        #pragma unroll
        for (int q = 0; q < 4; q++) {
            int im = q >> 1, hi = q & 1;
            int row = wm * 32 + im * 16 + hi * 8 + g;
            int n = n0 + row;
            if (n >= NN) continue;
            float* vp = g_v + (size_t)n * HC;
            #pragma unroll
            for (int jn = 0; jn < 4; jn++) {
                int col = wn * 32 + jn * 8 + 2 * r;
                float2 old = *(const float2*)(vp + col);
                float2 o;
                o.x = old.x + c[im][jn][hi * 2 + 0] + sB2[col];
                o.y = old.y + c[im][jn][hi * 2 + 1] + sB2[col + 1];
                *(float2*)(vp + col) = o;
                float2 t;
                t.x = __uint_as_float(f2tf32(o.x));
                t.y = __uint_as_float(f2tf32(o.y));
                *(float2*)(sA + row * SB + col) = t;
            }
        }
        if (!linW) return;
        __syncthreads();
    } else {
        for (int i = tid; i < NT * HC; i += 512) {
            int n = n0 + (i >> 7);
            sA[(i >> 7) * SB + (i & 127)] =
                (n < NN) ? __uint_as_float(f2tf32(g_v[(size_t)n * HC + (i & 127)])) : 0.0f;
        }
    }

    // GEMM C: x = v_new @ linW -> fp16
    for (int i = tid; i < HC * FC; i += 512)
        sW[(i >> 7) * SB + (i & 127)] = __uint_as_float(f2tf32(linW[i]));
    __syncthreads();

    #pragma unroll
    for (int im = 0; im < 2; im++)
        #pragma unroll
        for (int jn = 0; jn < 4; jn++)
            #pragma unroll
            for (int q = 0; q < 4; q++) c[im][jn][q] = 0.0f;
    #pragma unroll 4
    for (int kk = 0; kk < FC / 8; kk++) {
        uint32_t a[2][4];
        #pragma unroll
        for (int im = 0; im < 2; im++) {
            int rb = wm * 32 + im * 16 + g;
            int kb = kk * 8 + r;
            a[im][0] = __float_as_uint(sA[rb * SB + kb]);
            a[im][1] = __float_as_uint(sA[(rb + 8) * SB + kb]);
            a[im][2] = __float_as_uint(sA[rb * SB + kb + 4]);
            a[im][3] = __float_as_uint(sA[(rb + 8) * SB + kb + 4]);
        }
        #pragma unroll
        for (int jn = 0; jn < 4; jn++) {
            int nb = wn * 32 + jn * 8 + g;
            uint32_t b0 = __float_as_uint(sW[(kk * 8 + r) * SB + nb]);
            uint32_t bv = __float_as_uint(sW[(kk * 8 + 4 + r) * SB + nb]);
            mma8(c[0][jn], a[0], b0, bv);
            mma8(c[1][jn], a[1], b0, bv);
        }
    }
    #pragma unroll
    for (int q = 0; q < 4; q++) {
        int im = q >> 1, hi = q & 1;
        int row = wm * 32 + im * 16 + hi * 8 + g;
        int n = n0 + row;
        if (n >= NN) continue;
        unsigned int* xp = g_xh + (size_t)n * 64;
        #pragma unroll
        for (int jn = 0; jn < 4; jn++) {
            int col = wn * 32 + jn * 8 + 2 * r;
            __half2 h = __floats2half2_rn(c[im][jn][hi * 2 + 0], c[im][jn][hi * 2 + 1]);
            xp[col >> 1] = *(unsigned int*)&h;
        }
    }
}

// ---------------- readout ---------------------------------------------------
__global__ void readout_kernel(const int* __restrict__ batch,
                               const float* __restrict__ uW1, const float* __restrict__ ub1,
                               const float* __restrict__ uW2, const float* __restrict__ ub2,
                               float* __restrict__ out)
{
    __shared__ float sv[8][HC];
    int tid = threadIdx.x;
    int w = tid >> 5, l = tid & 31;
    int n0 = blockIdx.x * 8;
    for (int i = tid; i < 8 * HC; i += 256) {
        int n = n0 + (i >> 7);
        sv[i >> 7][i & 127] = (n < NN) ? g_v[(size_t)n * HC + (i & 127)] : 0.0f;
    }
    __syncthreads();
    int n = n0 + w;
    if (n >= NN) return;
    float a0 = 0.0f, a1 = 0.0f;
    #pragma unroll 8
    for (int h = 0; h < HC; h++) {
        float vv = sv[w][h];
        a0 += vv * uW1[h * 64 + l];
        a1 += vv * uW1[h * 64 + l + 32];
    }
    float h0 = ssp_f(a0 + ub1[l]);
    float h1 = ssp_f(a1 + ub1[l + 32]);
    float p = h0 * uW2[l] + h1 * uW2[l + 32];
    #pragma unroll
    for (int o = 16; o; o >>= 1) p += __shfl_down_sync(0xffffffffu, p, o);
    if (l == 0) atomicAdd(&out[batch[n]], p + ub2[0]);
}

// ---------------- launch ----------------------------------------------------
extern "C" void kernel_launch(void* const* d_in, const int* in_sizes, int n_in,
                              void* d_out, int out_size)
{
    const int*   z     = (const int*)d_in[0];
    const float* pos   = (const float*)d_in[1];
    const int*   batch = (const int*)d_in[2];
    const int*   eidx  = (const int*)d_in[3];
    const float* emb   = (const float*)d_in[4];
    const float* lin_W = (const float*)d_in[5];
    const float* mW1   = (const float*)d_in[6];
    const float* mb1   = (const float*)d_in[7];
    const float* mW2   = (const float*)d_in[8];
    const float* mb2   = (const float*)d_in[9];
    const float* vW1   = (const float*)d_in[10];
    const float* vb1   = (const float*)d_in[11];
    const float* vW2   = (const float*)d_in[12];
    const float* vb2   = (const float*)d_in[13];
    const float* uW1   = (const float*)d_in[14];
    const float* ub1   = (const float*)d_in[15];
    const float* uW2   = (const float*)d_in[16];
    const float* ub2   = (const float*)d_in[17];
    float* out = (float*)d_out;

    const int LUT_SMEM = LUT_SMEM_F * (int)sizeof(float);
    const int FUSED_SMEM = FUSED_SMEM_F * (int)sizeof(float);
    cudaFuncSetAttribute(lut_gen_kernel, cudaFuncAttributeMaxDynamicSharedMemorySize, LUT_SMEM);
    cudaFuncSetAttribute(layer_fused_kernel, cudaFuncAttributeMaxDynamicSharedMemorySize, FUSED_SMEM);

    init_v_kernel<<<(NN * HC + 255) / 256, 256>>>(z, emb);
    zero_cnt_kernel<<<(NN + 255) / 256, 256>>>();
    edge_pre_kernel<<<(NE + 255) / 256, 256>>>(pos, eidx);
    scan_part_kernel<<<SNB, SCB>>>();
    scan_top_kernel<<<1, 256>>>();
    scan_emit_kernel<<<SNB, SCB>>>();
    scatter_kernel<<<(NE + 255) / 256, 256>>>(eidx);
    prep_w_kernel<<<(NLAY * FC * FC + 255) / 256, 256>>>(mW1, mW2);
    lut_gen_kernel<<<dim3(NLUT / 128, NLAY), 256, LUT_SMEM>>>(mb1, mb2);

    const int NODE_GRID = (NN + NT - 1) / NT;   // 391
    unsigned int* lutDev;
    cudaGetSymbolAddress((void**)&lutDev, g_lut_h);

    layer_fused_kernel<<<NODE_GRID, 512, FUSED_SMEM>>>(nullptr, nullptr, nullptr, nullptr, lin_W, 0);
    for (int l = 0; l < NLAY; l++) {
        agg_gather_kernel<<<(NN + 7) / 8, 256>>>(lutDev + (size_t)l * NLUT * 64);
        const float* nextLin = (l + 1 < NLAY) ? (lin_W + (size_t)(l + 1) * HC * FC) : nullptr;
        layer_fused_kernel<<<NODE_GRID, 512, FUSED_SMEM>>>(
            vW1 + (size_t)l * FC * HC, vb1 + (size_t)l * HC,
            vW2 + (size_t)l * HC * HC, vb2 + (size_t)l * HC,
            nextLin, 1);
    }

    zero_out_kernel<<<1, 64>>>(out);
    readout_kernel<<<(NN + 7) / 8, 256>>>(batch, uW1, ub1, uW2, ub2, out);
    (void)in_sizes; (void)n_in; (void)out_size;
}

// round 9
// speedup vs baseline: 13.7707x; 1.2184x over previous
#include <cuda_runtime.h>
#include <cuda_fp16.h>
#include <math.h>
#include <stdint.h>

#define NN 50000
#define NE 625000
#define NGR 64
#define HC 128
#define FC 128
#define NGAUSS 50
#define KG 56                         // gaussian K padded to 56 (mult of 8)
#define NLAY 6
#define NT 128                        // node tile rows

#define NLUT 4096
#define DMAX 20.0f
#define LUT_STEP (DMAX / (float)NLUT)
#define INV_STEP ((float)NLUT / DMAX)

// smem strides
#define SA 60     // sD stride floats (lut_gen)
#define SB 132    // lut_gen weight/activation stride (floats)
#define SH2 68    // fused-kernel stride in half2 units (136 halves)

// ---------------- scratch (device globals; no allocation allowed) ----------
__device__ float g_v[NN * HC];
__device__ unsigned int g_xh[NN * 64];            // x = v@linW, fp16x2 packed
__device__ float g_agg[NN * HC];
__device__ float g_W1t[NLAY * KG * FC];           // lut_gen: [l][k][n] tf32
__device__ float g_W2t[NLAY * FC * FC];           // lut_gen: [l][k][n] tf32
__device__ unsigned int g_lut_h[(size_t)NLAY * NLUT * 64]; // fp16x2 LUT rows
// node weights, fp16, TRANSPOSED [l][n][k] packed half2 (64 per row)
__device__ unsigned int g_hLin[NLAY * 128 * 64];
__device__ unsigned int g_hW1[NLAY * 128 * 64];
__device__ unsigned int g_hW2[NLAY * 128 * 64];
// CSR edge structure (by destination node)
__device__ float g_uraw[NE];
__device__ int   g_cnt[NN];
__device__ int   g_fill[NN];
__device__ int   g_rowstart[NN + 1];
__device__ int   g_esrc[NE];
__device__ float g_eu[NE];
// scan temporaries
#define SCB 256
#define SNB 196
__device__ int g_bsum[SNB];
__device__ int g_boff[SNB];

// ---------------- helpers ---------------------------------------------------
__device__ __forceinline__ uint32_t f2tf32(float x) {
    uint32_t r;
    asm("cvt.rna.tf32.f32 %0, %1;" : "=r"(r) : "f"(x));
    return r;
}
__device__ __forceinline__ void mma8(float* c, const uint32_t* a, uint32_t b0, uint32_t b1) {
    asm volatile("mma.sync.aligned.m16n8k8.row.col.f32.tf32.tf32.f32 "
                 "{%0,%1,%2,%3},{%4,%5,%6,%7},{%8,%9},{%0,%1,%2,%3};"
                 : "+f"(c[0]), "+f"(c[1]), "+f"(c[2]), "+f"(c[3])
                 : "r"(a[0]), "r"(a[1]), "r"(a[2]), "r"(a[3]), "r"(b0), "r"(b1));
}
__device__ __forceinline__ void mma16(float* c, const uint32_t* a, uint32_t b0, uint32_t b1) {
    asm volatile("mma.sync.aligned.m16n8k16.row.col.f32.f16.f16.f32 "
                 "{%0,%1,%2,%3},{%4,%5,%6,%7},{%8,%9},{%0,%1,%2,%3};"
                 : "+f"(c[0]), "+f"(c[1]), "+f"(c[2]), "+f"(c[3])
                 : "r"(a[0]), "r"(a[1]), "r"(a[2]), "r"(a[3]), "r"(b0), "r"(b1));
}
__device__ __forceinline__ float ssp_f(float x) {
    return fmaxf(x, 0.0f) + log1pf(expf(-fabsf(x))) - 0.69314718055994531f;
}

// ---------------- init: v = emb_table[z] -----------------------------------
__global__ void init_v_kernel(const int* __restrict__ z, const float* __restrict__ emb) {
    int idx = blockIdx.x * blockDim.x + threadIdx.x;
    if (idx < NN * HC) g_v[idx] = emb[z[idx >> 7] * HC + (idx & 127)];
}

// ---------------- CSR build -------------------------------------------------
__global__ void zero_cnt_kernel() {
    int i = blockIdx.x * blockDim.x + threadIdx.x;
    if (i < NN) { g_cnt[i] = 0; g_fill[i] = 0; }
}

__global__ void edge_pre_kernel(const float* __restrict__ pos, const int* __restrict__ eidx) {
    int e = blockIdx.x * blockDim.x + threadIdx.x;
    if (e >= NE) return;
    int r = eidx[e], c = eidx[NE + e];
    float dx = pos[3 * r] - pos[3 * c];
    float dy = pos[3 * r + 1] - pos[3 * c + 1];
    float dz = pos[3 * r + 2] - pos[3 * c + 2];
    g_uraw[e] = sqrtf(dx * dx + dy * dy + dz * dz) * INV_STEP;
    atomicAdd(&g_cnt[c], 1);
}

__global__ void scan_part_kernel() {
    __shared__ int sh[SCB];
    int i = blockIdx.x * SCB + threadIdx.x;
    int v = (i < NN) ? g_cnt[i] : 0;
    sh[threadIdx.x] = v;
    __syncthreads();
    for (int off = SCB / 2; off; off >>= 1) {
        if (threadIdx.x < off) sh[threadIdx.x] += sh[threadIdx.x + off];
        __syncthreads();
    }
    if (threadIdx.x == 0) g_bsum[blockIdx.x] = sh[0];
}
__global__ void scan_top_kernel() {
    __shared__ int sh[256];
    int t = threadIdx.x;
    int v = (t < SNB) ? g_bsum[t] : 0;
    sh[t] = v;
    __syncthreads();
    for (int off = 1; off < 256; off <<= 1) {
        int u = (t >= off) ? sh[t - off] : 0;
        __syncthreads();
        sh[t] += u;
        __syncthreads();
    }
    if (t < SNB) g_boff[t] = sh[t] - v;
}
__global__ void scan_emit_kernel() {
    __shared__ int sh[SCB];
    int i = blockIdx.x * SCB + threadIdx.x;
    int v = (i < NN) ? g_cnt[i] : 0;
    sh[threadIdx.x] = v;
    __syncthreads();
    for (int off = 1; off < SCB; off <<= 1) {
        int u = (threadIdx.x >= off) ? sh[threadIdx.x - off] : 0;
        __syncthreads();
        sh[threadIdx.x] += u;
        __syncthreads();
    }
    if (i < NN) g_rowstart[i] = g_boff[blockIdx.x] + sh[threadIdx.x] - v;
    if (i == 0) g_rowstart[NN] = NE;
}

__global__ void scatter_kernel(const int* __restrict__ eidx) {
    int e = blockIdx.x * blockDim.x + threadIdx.x;
    if (e >= NE) return;
    int ci = eidx[NE + e];
    int pos = g_rowstart[ci] + atomicAdd(&g_fill[ci], 1);
    g_esrc[pos] = eidx[e];
    g_eu[pos] = g_uraw[e];
}

// ---------------- prep: lut weights (tf32) ----------------------------------
__global__ void prep_w_kernel(const float* __restrict__ mW1, const float* __restrict__ mW2) {
    int idx = blockIdx.x * blockDim.x + threadIdx.x;
    if (idx < NLAY * KG * FC) {
        int l = idx / (KG * FC), rem = idx % (KG * FC);
        int k = rem / FC, n = rem % FC;
        float v = (k < NGAUSS) ? mW1[(l * NGAUSS + k) * FC + n] : 0.0f;
        g_W1t[idx] = __uint_as_float(f2tf32(v));
    }
    if (idx < NLAY * FC * FC) {
        g_W2t[idx] = __uint_as_float(f2tf32(mW2[idx]));
    }
}

// ---------------- prep: node weights fp16 transposed [l][n][k] --------------
__global__ void prep_wh_kernel(const float* __restrict__ linW,
                               const float* __restrict__ vW1,
                               const float* __restrict__ vW2) {
    int idx = blockIdx.x * blockDim.x + threadIdx.x;
    if (idx >= NLAY * 128 * 64) return;
    int l = idx >> 13, rem = idx & 8191;
    int n = rem >> 6, c2 = rem & 63;
    int k = 2 * c2;
    const float* base;
    size_t off = (size_t)l * 16384;
    // lin
    base = linW + off;
    {
        __half2 h = __floats2half2_rn(base[k * 128 + n], base[(k + 1) * 128 + n]);
        g_hLin[idx] = *(unsigned int*)&h;
    }
    base = vW1 + off;
    {
        __half2 h = __floats2half2_rn(base[k * 128 + n], base[(k + 1) * 128 + n]);
        g_hW1[idx] = *(unsigned int*)&h;
    }
    base = vW2 + off;
    {
        __half2 h = __floats2half2_rn(base[k * 128 + n], base[(k + 1) * 128 + n]);
        g_hW2[idx] = *(unsigned int*)&h;
    }
}

__global__ void zero_out_kernel(float* __restrict__ out) {
    if (threadIdx.x < NGR) out[threadIdx.x] = 0.0f;
}

// ---------------- LUT generation (tf32 mma) ---------------------------------
#define OFF_SW1 0
#define OFF_SW2 (OFF_SW1 + KG * SB)
#define OFF_SD  (OFF_SW2 + FC * SB)
#define OFF_STT (OFF_SD + 128 * SA)
#define OFF_SB1 (OFF_STT + 128 * SB)
#define OFF_SB2 (OFF_SB1 + FC)
#define LUT_SMEM_F (OFF_SB2 + FC)

__global__ void __launch_bounds__(256, 1)
lut_gen_kernel(const float* __restrict__ mb1, const float* __restrict__ mb2)
{
    extern __shared__ float s[];
    float* sW1 = s + OFF_SW1;
    float* sW2 = s + OFF_SW2;
    float* sD  = s + OFF_SD;
    float* sT  = s + OFF_STT;
    float* sB1 = s + OFF_SB1;
    float* sB2 = s + OFF_SB2;

    int tid = threadIdx.x;
    int wid = tid >> 5, lane = tid & 31;
    int g = lane >> 2, r = lane & 3;
    int wm = wid & 3, wn = wid >> 2;
    int t = blockIdx.x;
    int l = blockIdx.y;

    {
        const float* w1 = g_W1t + (size_t)l * KG * FC;
        const float* w2 = g_W2t + (size_t)l * FC * FC;
        const float* b1 = mb1 + (size_t)l * FC;
        const float* b2 = mb2 + (size_t)l * FC;
        for (int i = tid; i < KG * FC; i += 256) sW1[(i >> 7) * SB + (i & 127)] = w1[i];
        for (int i = tid; i < FC * FC; i += 256) sW2[(i >> 7) * SB + (i & 127)] = w2[i];
        for (int i = tid; i < FC; i += 256) { sB1[i] = b1[i]; sB2[i] = b2[i]; }
    }
    {
        const float delta = 10.0f / 49.0f;
        const float coeff = -0.5f / (delta * delta);
        for (int i = tid; i < 128 * KG; i += 256) {
            int row = i / KG, k = i - row * KG;
            float d = (float)(t * 128 + row) * LUT_STEP;
            float dd = d - (float)k * delta;
            float v = (k < NGAUSS) ? expf(coeff * dd * dd) : 0.0f;
            sD[row * SA + k] = __uint_as_float(f2tf32(v));
        }
    }
    __syncthreads();

    float c1[2][8][4];
    #pragma unroll
    for (int im = 0; im < 2; im++)
        #pragma unroll
        for (int jn = 0; jn < 8; jn++)
            #pragma unroll
            for (int q = 0; q < 4; q++) c1[im][jn][q] = 0.0f;

    #pragma unroll
    for (int kk = 0; kk < KG / 8; kk++) {
        uint32_t a[2][4];
        #pragma unroll
        for (int im = 0; im < 2; im++) {
            int rb = wm * 32 + im * 16 + g;
            int kb = kk * 8 + r;
            a[im][0] = __float_as_uint(sD[rb * SA + kb]);
            a[im][1] = __float_as_uint(sD[(rb + 8) * SA + kb]);
            a[im][2] = __float_as_uint(sD[rb * SA + kb + 4]);
            a[im][3] = __float_as_uint(sD[(rb + 8) * SA + kb + 4]);
        }
        #pragma unroll
        for (int jn = 0; jn < 8; jn++) {
            int nb = wn * 64 + jn * 8 + g;
            uint32_t b0 = __float_as_uint(sW1[(kk * 8 + r) * SB + nb]);
            uint32_t bv = __float_as_uint(sW1[(kk * 8 + 4 + r) * SB + nb]);
            mma8(c1[0][jn], a[0], b0, bv);
            mma8(c1[1][jn], a[1], b0, bv);
        }
    }

    #pragma unroll
    for (int im = 0; im < 2; im++) {
        int rb = wm * 32 + im * 16 + g;
        #pragma unroll
        for (int jn = 0; jn < 8; jn++) {
            int col = wn * 64 + jn * 8 + 2 * r;
            float bb0 = sB1[col], bb1 = sB1[col + 1];
            float2 lo, hi;
            lo.x = __uint_as_float(f2tf32(ssp_f(c1[im][jn][0] + bb0)));
            lo.y = __uint_as_float(f2tf32(ssp_f(c1[im][jn][1] + bb1)));
            hi.x = __uint_as_float(f2tf32(ssp_f(c1[im][jn][2] + bb0)));
            hi.y = __uint_as_float(f2tf32(ssp_f(c1[im][jn][3] + bb1)));
            *(float2*)(sT + rb * SB + col) = lo;
            *(float2*)(sT + (rb + 8) * SB + col) = hi;
        }
    }
    __syncthreads();

    float c2[2][8][4];
    #pragma unroll
    for (int im = 0; im < 2; im++)
        #pragma unroll
        for (int jn = 0; jn < 8; jn++)
            #pragma unroll
            for (int q = 0; q < 4; q++) c2[im][jn][q] = 0.0f;

    #pragma unroll 4
    for (int kk = 0; kk < FC / 8; kk++) {
        uint32_t a[2][4];
        #pragma unroll
        for (int im = 0; im < 2; im++) {
            int rb = wm * 32 + im * 16 + g;
            int kb = kk * 8 + r;
            a[im][0] = __float_as_uint(sT[rb * SB + kb]);
            a[im][1] = __float_as_uint(sT[(rb + 8) * SB + kb]);
            a[im][2] = __float_as_uint(sT[rb * SB + kb + 4]);
            a[im][3] = __float_as_uint(sT[(rb + 8) * SB + kb + 4]);
        }
        #pragma unroll
        for (int jn = 0; jn < 8; jn++) {
            int nb = wn * 64 + jn * 8 + g;
            uint32_t b0 = __float_as_uint(sW2[(kk * 8 + r) * SB + nb]);
            uint32_t bv = __float_as_uint(sW2[(kk * 8 + 4 + r) * SB + nb]);
            mma8(c2[0][jn], a[0], b0, bv);
            mma8(c2[1][jn], a[1], b0, bv);
        }
    }

    unsigned int* lutL = g_lut_h + (size_t)l * NLUT * 64;
    #pragma unroll
    for (int q = 0; q < 4; q++) {
        int im = q >> 1, hi = q & 1;
        int row = wm * 32 + im * 16 + hi * 8 + g;
        int idx = t * 128 + row;
        float d = (float)idx * LUT_STEP;
        float Ce = 0.5f * (cosf(d * 0.31415926535897931f) + 1.0f);
        unsigned int* lp = lutL + (size_t)idx * 64;
        #pragma unroll
        for (int jn = 0; jn < 8; jn++) {
            int col = wn * 64 + jn * 8 + 2 * r;
            float ox = (c2[im][jn][hi * 2 + 0] + sB2[col]) * Ce;
            float oy = (c2[im][jn][hi * 2 + 1] + sB2[col + 1]) * Ce;
            __half2 h = __floats2half2_rn(ox, oy);
            lp[col >> 1] = *(unsigned int*)&h;
        }
    }
}

// ---------------- agg gather: warp per node, fp16 LUT + fp16 x --------------
__global__ void __launch_bounds__(256)
agg_gather_kernel(const unsigned int* __restrict__ lut)
{
    int node = blockIdx.x * 8 + (threadIdx.x >> 5);
    if (node >= NN) return;
    int lane = threadIdx.x & 31;
    int s = g_rowstart[node], e = g_rowstart[node + 1];
    float4 acc = make_float4(0.0f, 0.0f, 0.0f, 0.0f);
    #pragma unroll 4
    for (int k = s; k < e; k++) {
        int rj = g_esrc[k];
        float u = g_eu[k];
        int i0 = (int)u;
        i0 = (i0 > NLUT - 2) ? (NLUT - 2) : i0;
        float f = u - (float)i0;
        const uint2* la = (const uint2*)(lut + (size_t)i0 * 64) + lane;
        uint2 A = la[0];
        uint2 B = la[32];
        uint2 X = ((const uint2*)(g_xh + (size_t)rj * 64))[lane];
        float2 a0 = __half22float2(*(__half2*)&A.x);
        float2 a1 = __half22float2(*(__half2*)&A.y);
        float2 b0 = __half22float2(*(__half2*)&B.x);
        float2 b1 = __half22float2(*(__half2*)&B.y);
        float2 x0 = __half22float2(*(__half2*)&X.x);
        float2 x1 = __half22float2(*(__half2*)&X.y);
        acc.x = fmaf(fmaf(f, b0.x - a0.x, a0.x), x0.x, acc.x);
        acc.y = fmaf(fmaf(f, b0.y - a0.y, a0.y), x0.y, acc.y);
        acc.z = fmaf(fmaf(f, b1.x - a1.x, a1.x), x1.x, acc.z);
        acc.w = fmaf(fmaf(f, b1.y - a1.y, a1.y), x1.y, acc.w);
    }
    ((float4*)(g_agg + (size_t)node * HC))[lane] = acc;
}

// ---------------- fused per-layer node kernel (fp16 m16n8k16) ---------------
// full=1: g_v += ssp(agg@W1+b1)@W2+b2 ; then (if linWh) g_xh = fp16(v@lin)
// full=0: g_xh = fp16(g_v @ lin) only
// smem: 3 half2 buffers [128][SH2] + 2 fp32 bias rows
#define FUS_U_W 0
#define FUS_U_A (128 * SH2)
#define FUS_U_H (2 * 128 * SH2)
#define FUS_U_B (3 * 128 * SH2)
#define FUSED_SMEM_B ((FUS_U_B + 256) * 4)

__global__ void __launch_bounds__(512, 2)
layer_fused_kernel(const unsigned int* __restrict__ W1h, const float* __restrict__ b1,
                   const unsigned int* __restrict__ W2h, const float* __restrict__ b2,
                   const unsigned int* __restrict__ linWh, int full)
{
    extern __shared__ unsigned int su[];
    unsigned int* sW = su + FUS_U_W;
    unsigned int* sA = su + FUS_U_A;
    unsigned int* sH = su + FUS_U_H;
    float* sB1 = (float*)(su + FUS_U_B);
    float* sB2 = sB1 + 128;

    int tid = threadIdx.x;
    int wid = tid >> 5, lane = tid & 31;
    int g = lane >> 2, r = lane & 3;
    int wm = wid & 3, wn = wid >> 2;   // 4x4 warp grid, 32x32 tiles
    int n0 = blockIdx.x * NT;

    float c[2][4][4];

    if (full) {
        // stage agg -> sA (fp16)
        for (int i = tid; i < 128 * 64; i += 512) {
            int row = i >> 6, c2 = i & 63;
            int n = n0 + row;
            float2 vv = (n < NN) ? *(const float2*)(g_agg + (size_t)n * HC + 2 * c2)
                                 : make_float2(0.0f, 0.0f);
            __half2 h = __floats2half2_rn(vv.x, vv.y);
            sA[row * SH2 + c2] = *(unsigned int*)&h;
        }
        for (int i = tid; i < 128 * 64; i += 512)
            sW[(i >> 6) * SH2 + (i & 63)] = W1h[i];
        if (tid < FC) sB1[tid] = b1[tid];
        else if (tid >= 128 && tid < 256) sB2[tid - 128] = b2[tid - 128];
        __syncthreads();

        // GEMM A: h = ssp(agg @ W1 + b1)
        #pragma unroll
        for (int im = 0; im < 2; im++)
            #pragma unroll
            for (int jn = 0; jn < 4; jn++)
                #pragma unroll
                for (int q = 0; q < 4; q++) c[im][jn][q] = 0.0f;
        #pragma unroll
        for (int kk = 0; kk < 8; kk++) {
            uint32_t a[2][4];
            #pragma unroll
            for (int im = 0; im < 2; im++) {
                int rb = wm * 32 + im * 16 + g;
                a[im][0] = sA[rb * SH2 + kk * 8 + r];
                a[im][1] = sA[(rb + 8) * SH2 + kk * 8 + r];
                a[im][2] = sA[rb * SH2 + kk * 8 + 4 + r];
                a[im][3] = sA[(rb + 8) * SH2 + kk * 8 + 4 + r];
            }
            #pragma unroll
            for (int jn = 0; jn < 4; jn++) {
                int nb = wn * 32 + jn * 8 + g;
                uint32_t b0 = sW[nb * SH2 + kk * 8 + r];
                uint32_t bv = sW[nb * SH2 + kk * 8 + 4 + r];
                mma16(c[0][jn], a[0], b0, bv);
                mma16(c[1][jn], a[1], b0, bv);
            }
        }
        #pragma unroll
        for (int q = 0; q < 4; q++) {
            int im = q >> 1, hi = q & 1;
            int row = wm * 32 + im * 16 + hi * 8 + g;
            #pragma unroll
            for (int jn = 0; jn < 4; jn++) {
                int col = wn * 32 + jn * 8 + 2 * r;
                __half2 h = __floats2half2_rn(ssp_f(c[im][jn][hi * 2 + 0] + sB1[col]),
                                              ssp_f(c[im][jn][hi * 2 + 1] + sB1[col + 1]));
                sH[row * SH2 + (col >> 1)] = *(unsigned int*)&h;
            }
        }
        __syncthreads();
        for (int i = tid; i < 128 * 64; i += 512)
            sW[(i >> 6) * SH2 + (i & 63)] = W2h[i];
        __syncthreads();

        // GEMM B: v += h @ W2 + b2 ; sA = fp16(v_new)
        #pragma unroll
        for (int im = 0; im < 2; im++)
            #pragma unroll
            for (int jn = 0; jn < 4; jn++)
                #pragma unroll
                for (int q = 0; q < 4; q++) c[im][jn][q] = 0.0f;
        #pragma unroll
        for (int kk = 0; kk < 8; kk++) {
            uint32_t a[2][4];
            #pragma unroll
            for (int im = 0; im < 2; im++) {
                int rb = wm * 32 + im * 16 + g;
                a[im][0] = sH[rb * SH2 + kk * 8 + r];
                a[im][1] = sH[(rb + 8) * SH2 + kk * 8 + r];
                a[im][2] = sH[rb * SH2 + kk * 8 + 4 + r];
                a[im][3] = sH[(rb + 8) * SH2 + kk * 8 + 4 + r];
            }
            #pragma unroll
            for (int jn = 0; jn < 4; jn++) {
                int nb = wn * 32 + jn * 8 + g;
                uint32_t b0 = sW[nb * SH2 + kk * 8 + r];
                uint32_t bv = sW[nb * SH2 + kk * 8 + 4 + r];
                mma16(c[0][jn], a[0], b0, bv);
                mma16(c[1][jn], a[1], b0, bv);
            }
        }
        #pragma unroll
        for (int q = 0; q < 4; q++) {
            int im = q >> 1, hi = q & 1;
            int row = wm * 32 + im * 16 + hi * 8 + g;
            int n = n0 + row;
            if (n >= NN) continue;
            float* vp = g_v + (size_t)n * HC;
            #pragma unroll
            for (int jn = 0; jn < 4; jn++) {
                int col = wn * 32 + jn * 8 + 2 * r;
                float2 old = *(const float2*)(vp + col);
                float2 o;
                o.x = old.x + c[im][jn][hi * 2 + 0] + sB2[col];
                o.y = old.y + c[im][jn][hi * 2 + 1] + sB2[col + 1];
                *(float2*)(vp + col) = o;
                __half2 h = __floats2half2_rn(o.x, o.y);
                sA[row * SH2 + (col >> 1)] = *(unsigned int*)&h;
            }
        }
        if (!linWh) return;
        __syncthreads();
    } else {
        for (int i = tid; i < 128 * 64; i += 512) {
            int row = i >> 6, c2 = i & 63;
            int n = n0 + row;
            float2 vv = (n < NN) ? *(const float2*)(g_v + (size_t)n * HC + 2 * c2)
                                 : make_float2(0.0f, 0.0f);
            __half2 h = __floats2half2_rn(vv.x, vv.y);
            sA[row * SH2 + c2] = *(unsigned int*)&h;
        }
    }

    // GEMM C: x = v_new @ lin -> fp16 to g_xh
    for (int i = tid; i < 128 * 64; i += 512)
        sW[(i >> 6) * SH2 + (i & 63)] = linWh[i];
    __syncthreads();

    #pragma unroll
    for (int im = 0; im < 2; im++)
        #pragma unroll
        for (int jn = 0; jn < 4; jn++)
            #pragma unroll
            for (int q = 0; q < 4; q++) c[im][jn][q] = 0.0f;
    #pragma unroll
    for (int kk = 0; kk < 8; kk++) {
        uint32_t a[2][4];
        #pragma unroll
        for (int im = 0; im < 2; im++) {
            int rb = wm * 32 + im * 16 + g;
            a[im][0] = sA[rb * SH2 + kk * 8 + r];
            a[im][1] = sA[(rb + 8) * SH2 + kk * 8 + r];
            a[im][2] = sA[rb * SH2 + kk * 8 + 4 + r];
            a[im][3] = sA[(rb + 8) * SH2 + kk * 8 + 4 + r];
        }
        #pragma unroll
        for (int jn = 0; jn < 4; jn++) {
            int nb = wn * 32 + jn * 8 + g;
            uint32_t b0 = sW[nb * SH2 + kk * 8 + r];
            uint32_t bv = sW[nb * SH2 + kk * 8 + 4 + r];
            mma16(c[0][jn], a[0], b0, bv);
            mma16(c[1][jn], a[1], b0, bv);
        }
    }
    #pragma unroll
    for (int q = 0; q < 4; q++) {
        int im = q >> 1, hi = q & 1;
        int row = wm * 32 + im * 16 + hi * 8 + g;
        int n = n0 + row;
        if (n >= NN) continue;
        unsigned int* xp = g_xh + (size_t)n * 64;
        #pragma unroll
        for (int jn = 0; jn < 4; jn++) {
            int col = wn * 32 + jn * 8 + 2 * r;
            __half2 h = __floats2half2_rn(c[im][jn][hi * 2 + 0], c[im][jn][hi * 2 + 1]);
            xp[col >> 1] = *(unsigned int*)&h;
        }
    }
}

// ---------------- readout ---------------------------------------------------
__global__ void readout_kernel(const int* __restrict__ batch,
                               const float* __restrict__ uW1, const float* __restrict__ ub1,
                               const float* __restrict__ uW2, const float* __restrict__ ub2,
                               float* __restrict__ out)
{
    __shared__ float sv[8][HC];
    int tid = threadIdx.x;
    int w = tid >> 5, l = tid & 31;
    int n0 = blockIdx.x * 8;
    for (int i = tid; i < 8 * HC; i += 256) {
        int n = n0 + (i >> 7);
        sv[i >> 7][i & 127] = (n < NN) ? g_v[(size_t)n * HC + (i & 127)] : 0.0f;
    }
    __syncthreads();
    int n = n0 + w;
    if (n >= NN) return;
    float a0 = 0.0f, a1 = 0.0f;
    #pragma unroll 8
    for (int h = 0; h < HC; h++) {
        float vv = sv[w][h];
        a0 += vv * uW1[h * 64 + l];
        a1 += vv * uW1[h * 64 + l + 32];
    }
    float h0 = ssp_f(a0 + ub1[l]);
    float h1 = ssp_f(a1 + ub1[l + 32]);
    float p = h0 * uW2[l] + h1 * uW2[l + 32];
    #pragma unroll
    for (int o = 16; o; o >>= 1) p += __shfl_down_sync(0xffffffffu, p, o);
    if (l == 0) atomicAdd(&out[batch[n]], p + ub2[0]);
}

// ---------------- launch ----------------------------------------------------
extern "C" void kernel_launch(void* const* d_in, const int* in_sizes, int n_in,
                              void* d_out, int out_size)
{
    const int*   z     = (const int*)d_in[0];
    const float* pos   = (const float*)d_in[1];
    const int*   batch = (const int*)d_in[2];
    const int*   eidx  = (const int*)d_in[3];
    const float* emb   = (const float*)d_in[4];
    const float* lin_W = (const float*)d_in[5];
    const float* mW1   = (const float*)d_in[6];
    const float* mb1   = (const float*)d_in[7];
    const float* mW2   = (const float*)d_in[8];
    const float* mb2   = (const float*)d_in[9];
    const float* vW1   = (const float*)d_in[10];
    const float* vb1   = (const float*)d_in[11];
    const float* vW2   = (const float*)d_in[12];
    const float* vb2   = (const float*)d_in[13];
    const float* uW1   = (const float*)d_in[14];
    const float* ub1   = (const float*)d_in[15];
    const float* uW2   = (const float*)d_in[16];
    const float* ub2   = (const float*)d_in[17];
    float* out = (float*)d_out;

    const int LUT_SMEM = LUT_SMEM_F * (int)sizeof(float);
    cudaFuncSetAttribute(lut_gen_kernel, cudaFuncAttributeMaxDynamicSharedMemorySize, LUT_SMEM);
    cudaFuncSetAttribute(layer_fused_kernel, cudaFuncAttributeMaxDynamicSharedMemorySize, FUSED_SMEM_B);

    init_v_kernel<<<(NN * HC + 255) / 256, 256>>>(z, emb);
    zero_cnt_kernel<<<(NN + 255) / 256, 256>>>();
    edge_pre_kernel<<<(NE + 255) / 256, 256>>>(pos, eidx);
    scan_part_kernel<<<SNB, SCB>>>();
    scan_top_kernel<<<1, 256>>>();
    scan_emit_kernel<<<SNB, SCB>>>();
    scatter_kernel<<<(NE + 255) / 256, 256>>>(eidx);
    prep_w_kernel<<<(NLAY * FC * FC + 255) / 256, 256>>>(mW1, mW2);
    prep_wh_kernel<<<(NLAY * 128 * 64 + 255) / 256, 256>>>(lin_W, vW1, vW2);
    lut_gen_kernel<<<dim3(NLUT / 128, NLAY), 256, LUT_SMEM>>>(mb1, mb2);

    const int NODE_GRID = (NN + NT - 1) / NT;   // 391
    unsigned int* lutDev;
    cudaGetSymbolAddress((void**)&lutDev, g_lut_h);
    unsigned int *hLin, *hW1, *hW2;
    cudaGetSymbolAddress((void**)&hLin, g_hLin);
    cudaGetSymbolAddress((void**)&hW1, g_hW1);
    cudaGetSymbolAddress((void**)&hW2, g_hW2);

    layer_fused_kernel<<<NODE_GRID, 512, FUSED_SMEM_B>>>(nullptr, nullptr, nullptr, nullptr, hLin, 0);
    for (int l = 0; l < NLAY; l++) {
        agg_gather_kernel<<<(NN + 7) / 8, 256>>>(lutDev + (size_t)l * NLUT * 64);
        const unsigned int* nextLin = (l + 1 < NLAY) ? (hLin + (size_t)(l + 1) * 8192) : nullptr;
        layer_fused_kernel<<<NODE_GRID, 512, FUSED_SMEM_B>>>(
            hW1 + (size_t)l * 8192, vb1 + (size_t)l * HC,
            hW2 + (size_t)l * 8192, vb2 + (size_t)l * HC,
            nextLin, 1);
    }

    zero_out_kernel<<<1, 64>>>(out);
    readout_kernel<<<(NN + 7) / 8, 256>>>(batch, uW1, ub1, uW2, ub2, out);
    (void)in_sizes; (void)n_in; (void)out_size;
}